// round 15
// baseline (speedup 1.0000x reference)
#include <cuda_runtime.h>
#include <math.h>

#define NSTA 4096
#define NCIT 256
#define NB 8
#define TH 8
#define TP 24
#define TT 32
#define DIN 28
#define DM 27
#define GF 64
#define HH 64
#define NG 192
#define DGRU 92
#define THIST 7
#define NNZMAX (1<<20)

#define NBLK   148
#define NBLK_S 128
#define NBLK_C 20
#define NTHR   1024
#define XS     130     // smem tile row-stride

#define SPS (NB*NSTA*DIN)
#define SPC (NB*NCIT*DIN)
#define RS  (NB*NSTA)
#define RC  (NB*NCIT)

typedef unsigned long long ull;

// ---------------- static device scratch ----------------
__device__ float g_dinv_s[NSTA];
__device__ int   g_cnt_s[NSTA];
__device__ int   g_Ls_rowptr[NSTA+1];
__device__ int   g_Ls_cols[NNZMAX];
__device__ float g_Ls_vals[NNZMAX];

__device__ int   g_cnt_afc[NSTA];
__device__ int   g_afc_rowptr[NSTA+1];
__device__ int   g_afc_cols[NNZMAX];

__device__ int   g_cnt_afcT[NCIT];
__device__ int   g_afcT_rowptr[NCIT+1];
__device__ int   g_afcT_cols[NNZMAX];

__device__ float g_dinv_c[NCIT];
__device__ int   g_cnt_c[NCIT];
__device__ float g_Lc[NCIT*NCIT];

// history buffers
__device__ float g_xs [THIST*RS*DIN];
__device__ float g_Lxs[THIST*RS*DIN];
__device__ float g_xgs[THIST*RS*GF];
__device__ float g_zsh[THIST*RS*GF];

__device__ float g_xc [THIST*RC*DIN];
__device__ float g_Lxc[THIST*RC*DIN];
__device__ float g_xgc[THIST*RC*GF];
__device__ float g_zch[THIST*RC*GF];

// pred precomputed x / Lx (all 24 steps)
__device__ float g_pxs [TP*SPS];
__device__ float g_pLxs[TP*SPS];
__device__ float g_pxc [TP*SPC];
__device__ float g_pLxc[TP*SPC];

__device__ float g_hs[RS*HH];
__device__ float g_hc[RC*HH];
__device__ float g_ys[RS];
__device__ float g_yc[RC];

// grid barrier state
__device__ unsigned g_bar_cnt = 0;
__device__ volatile unsigned g_bar_gen = 0;

// ---------------- helpers ----------------
__device__ __forceinline__ ull splat2(float w) {
    ull r;
    asm("mov.b64 %0, {%1, %1};" : "=l"(r) : "f"(w));
    return r;
}
__device__ __forceinline__ void fma2(ull& a, ull x, ull w) {
    asm("fma.rn.f32x2 %0, %1, %2, %0;" : "+l"(a) : "l"(x), "l"(w));
}
__device__ __forceinline__ float2 unp2(ull v) {
    float2 f;
    asm("mov.b64 {%0, %1}, %2;" : "=f"(f.x), "=f"(f.y) : "l"(v));
    return f;
}
__device__ __forceinline__ float sigm(float x) { return 1.f / (1.f + __expf(-x)); }

__device__ __forceinline__ void gbar() {
    __syncthreads();
    if (threadIdx.x == 0) {
        unsigned gen = g_bar_gen;
        __threadfence();
        unsigned t = atomicAdd(&g_bar_cnt, 1);
        if (t == (unsigned)(NBLK - 1)) {
            g_bar_cnt = 0;
            __threadfence();
            g_bar_gen = gen + 1;
        } else {
            while (g_bar_gen == gen) { __nanosleep(64); }
        }
    }
    __syncthreads();
    __threadfence();
}

__device__ __forceinline__ int wredi(int c) {
    #pragma unroll
    for (int o = 16; o; o >>= 1) c += __shfl_xor_sync(0xffffffffu, c, o);
    return c;
}

// ---------------- preproc device functions ----------------
__device__ __noinline__ void counts_phase(const float* adj_sta, const float* afc,
                                          const float* adj_city) {
    int gw = (blockIdx.x*NTHR + threadIdx.x) >> 5;
    int lane = threadIdx.x & 31;
    const int NW = NBLK*(NTHR/32);
    for (int m = gw; m < NSTA; m += NW) {
        int c = 0;
        const float* row = adj_sta + (size_t)m*NSTA;
        for (int j = lane; j < NSTA; j += 32) c += (row[j] != 0.f && j != m);
        c = wredi(c);
        if (lane == 0) { g_cnt_s[m] = c; g_dinv_s[m] = c > 0 ? rsqrtf((float)c) : 0.f; }
    }
    for (int m = gw; m < NSTA; m += NW) {
        int c = 0;
        const float* row = afc + (size_t)m*NCIT;
        for (int j = lane; j < NCIT; j += 32) c += (row[j] != 0.f);
        c = wredi(c);
        if (lane == 0) g_cnt_afc[m] = c;
    }
    for (int cc = gw; cc < NCIT; cc += NW) {
        int c = 0;
        for (int s = lane; s < NSTA; s += 32) c += (afc[(size_t)s*NCIT + cc] != 0.f);
        c = wredi(c);
        if (lane == 0) g_cnt_afcT[cc] = c;
    }
    for (int m = gw; m < NCIT; m += NW) {
        int c = 0;
        const float* row = adj_city + (size_t)m*NCIT;
        for (int j = lane; j < NCIT; j += 32) c += (row[j] != 0.f && j != m);
        c = wredi(c);
        if (lane == 0) { g_cnt_c[m] = c; g_dinv_c[m] = c > 0 ? rsqrtf((float)c) : 0.f; }
    }
}

__device__ __noinline__ void scan_phase(float* scratch) {
    if (blockIdx.x >= 3) return;
    int* s = (int*)scratch;
    const int* cnt; int* rp; int n;
    if (blockIdx.x == 0) { cnt = g_cnt_s; rp = g_Ls_rowptr; n = NSTA; }
    else if (blockIdx.x == 1) { cnt = g_cnt_afc; rp = g_afc_rowptr; n = NSTA; }
    else { cnt = g_cnt_afcT; rp = g_afcT_rowptr; n = NCIT; }
    int tid = threadIdx.x;
    int per = (n + NTHR - 1) / NTHR;
    int base = tid * per;
    int loc = 0;
    for (int i = 0; i < per; i++) if (base + i < n) loc += cnt[base + i];
    s[tid] = loc; __syncthreads();
    for (int off = 1; off < NTHR; off <<= 1) {
        int v = (tid >= off) ? s[tid - off] : 0;
        __syncthreads();
        s[tid] += v;
        __syncthreads();
    }
    int a = tid ? s[tid - 1] : 0;
    for (int i = 0; i < per; i++)
        if (base + i < n) { rp[base + i] = a; a += cnt[base + i]; }
    if (tid == NTHR - 1) rp[n] = a;
}

__device__ void fill_csr_row(const float* __restrict__ mat, const int* __restrict__ rowptr,
                             int* __restrict__ cols, float* __restrict__ vals,
                             const float* __restrict__ dinv,
                             int ncols, int excl, int m) {
    int lane = threadIdx.x & 31;
    int pos = rowptr[m];
    float dm = dinv ? dinv[m] : 0.f;
    for (int base = 0; base < ncols; base += 32) {
        int j = base + lane;
        bool p = (j < ncols) && (mat[(size_t)m*ncols + j] != 0.f) && !(excl && j == m);
        unsigned msk = __ballot_sync(0xffffffffu, p);
        if (p) {
            int off = __popc(msk & ((1u << lane) - 1u));
            cols[pos + off] = j;
            if (vals) vals[pos + off] = -dm * dinv[j];
        }
        pos += __popc(msk);
    }
}

__device__ void fill_csrT_col(const float* __restrict__ mat, const int* __restrict__ rowptr,
                              int* __restrict__ cols, int nrows, int ncols, int c) {
    int lane = threadIdx.x & 31;
    int pos = rowptr[c];
    for (int base = 0; base < nrows; base += 32) {
        int s = base + lane;
        bool p = (s < nrows) && (mat[(size_t)s*ncols + c] != 0.f);
        unsigned msk = __ballot_sync(0xffffffffu, p);
        if (p) cols[pos + __popc(msk & ((1u << lane) - 1u))] = s;
        pos += __popc(msk);
    }
}

__device__ __noinline__ void fills_phase(const float* adj_sta, const float* afc,
                                         const float* adj_city) {
    int gw = (blockIdx.x*NTHR + threadIdx.x) >> 5;
    const int NW = NBLK*(NTHR/32);
    for (int m = gw; m < NSTA; m += NW)
        fill_csr_row(adj_sta, g_Ls_rowptr, g_Ls_cols, g_Ls_vals, g_dinv_s, NSTA, 1, m);
    for (int m = gw; m < NSTA; m += NW)
        fill_csr_row(afc, g_afc_rowptr, g_afc_cols, nullptr, nullptr, NCIT, 0, m);
    for (int c = gw; c < NCIT; c += NW)
        fill_csrT_col(afc, g_afcT_rowptr, g_afcT_cols, NSTA, NCIT, c);
    int g = blockIdx.x*NTHR + threadIdx.x;
    for (int i = g; i < NCIT*NCIT; i += NBLK*NTHR) {
        int m = i >> 8, n = i & 255;
        float v = 0.f;
        if (n != m && adj_city[i] != 0.f) v = -g_dinv_c[m]*g_dinv_c[n];
        g_Lc[i] = v;
    }
}

__device__ __noinline__ void hist_stage_phase(const float* xh_s, const float* ft_s,
                                              const float* xh_c, const float* ft_c) {
    int g = blockIdx.x*NTHR + threadIdx.x;
    const int GS = NBLK*NTHR;
    const int nS = THIST*RS*DIN;
    for (int i = g; i < nS; i += GS) {
        int ch = i % DIN; int r = i / DIN; int n = r % NSTA; int tb = r / NSTA;
        int b = tb % NB; int t = tb / NB;
        g_xs[i] = (ch == 0) ? xh_s[(b*TH + t)*NSTA + n]
                            : ft_s[((size_t)(b*TT + (t+1))*NSTA + n)*DM + (ch-1)];
    }
    const int nC = THIST*RC*DIN;
    for (int i = g; i < nC; i += GS) {
        int ch = i % DIN; int r = i / DIN; int n = r % NCIT; int tb = r / NCIT;
        int b = tb % NB; int t = tb / NB;
        g_xc[i] = (ch == 0) ? xh_c[(b*TH + t)*NCIT + n]
                            : ft_c[((size_t)(b*TT + (t+1))*NCIT + n)*DM + (ch-1)];
    }
}

__device__ __noinline__ void buildpx_phase(const float* ft_s, const float* ft_c) {
    int g = blockIdx.x*NTHR + threadIdx.x;
    const int GS = NBLK*NTHR;
    const int totS = TP*NB*NSTA*DM;
    for (int i = g; i < totS; i += GS) {
        int ch = i % DM; int q = i / DM;
        int n = q & (NSTA-1); q >>= 12;
        int b = q & 7; int s = q >> 3;
        g_pxs[((size_t)(s*NB+b)*NSTA + n)*DIN + 1 + ch] =
            ft_s[(((size_t)b*TT + TH + s)*NSTA + n)*DM + ch];
    }
    const int totC = TP*NB*NCIT*DM;
    for (int i = g; i < totC; i += GS) {
        int ch = i % DM; int q = i / DM;
        int n = q & (NCIT-1); q >>= 8;
        int b = q & 7; int s = q >> 3;
        g_pxc[((size_t)(s*NB+b)*NCIT + n)*DIN + 1 + ch] =
            ft_c[(((size_t)b*TT + TH + s)*NCIT + n)*DM + ch];
    }
}

// histL + pred feature pLx + h/y init
__device__ __noinline__ void prep2_phase(const float* x_hist, const float* c_x_hist) {
    int gw = (blockIdx.x*NTHR + threadIdx.x) >> 5;
    int lane = threadIdx.x & 31;
    const int NW = NBLK*(NTHR/32);
    const int tasks = NSTA*THIST*NB;
    for (int t = gw; t < tasks; t += NW) {
        int m = t / (THIST*NB);
        int tb = t % (THIST*NB);
        int beg = g_Ls_rowptr[m], end = g_Ls_rowptr[m+1];
        const float* xb = g_xs + (size_t)tb*NSTA*DIN;
        if (lane < DIN) {
            float acc = 0.f;
            for (int p = beg; p < end; p++)
                acc += g_Ls_vals[p] * xb[g_Ls_cols[p]*DIN + lane];
            g_Lxs[((size_t)tb*NSTA + m)*DIN + lane] = acc;
        }
    }
    const int ptasks = TP*RS;
    for (int t = gw; t < ptasks; t += NW) {
        int n = t & (NSTA-1); int q = t >> 12;
        int b = q & 7; int s = q >> 3;
        int beg = g_Ls_rowptr[n], end = g_Ls_rowptr[n+1];
        const float* xb = g_pxs + (size_t)(s*NB+b)*NSTA*DIN;
        if (lane < DM) {
            float acc = 0.f;
            for (int p = beg; p < end; p++)
                acc += g_Ls_vals[p] * xb[g_Ls_cols[p]*DIN + 1 + lane];
            g_pLxs[((size_t)(s*NB+b)*NSTA + n)*DIN + 1 + lane] = acc;
        }
    }
    int g = blockIdx.x*NTHR + threadIdx.x;
    const int GS = NBLK*NTHR;
    for (int i = g; i < THIST*RC*DIN; i += GS) {
        int ch = i % DIN; int r = i / DIN; int m = r % NCIT; int tb = r / NCIT;
        const float* xb = g_xc + (size_t)tb*NCIT*DIN;
        float acc = 0.f;
        for (int j = 0; j < NCIT; j++) acc += g_Lc[m*NCIT + j]*xb[j*DIN + ch];
        g_Lxc[i] = acc;
    }
    for (int i = g; i < TP*RC*DM; i += GS) {
        int ch = i % DM; int q = i / DM;
        int n = q & (NCIT-1); q >>= 8;
        int b = q & 7; int s = q >> 3;
        const float* xb = g_pxc + (size_t)(s*NB+b)*NCIT*DIN;
        float acc = 0.f;
        for (int j = 0; j < NCIT; j++) acc += g_Lc[n*NCIT + j]*xb[j*DIN + 1 + ch];
        g_pLxc[((size_t)(s*NB+b)*NCIT + n)*DIN + 1 + ch] = acc;
    }
    for (int i = g; i < RS*HH; i += GS) g_hs[i] = 0.f;
    for (int i = g; i < RC*HH; i += GS) g_hc[i] = 0.f;
    for (int i = g; i < RS; i += GS) {
        int b = i >> 12, n = i & (NSTA-1);
        float y = x_hist[(b*TH + TH-1)*NSTA + n];
        g_ys[i] = y; g_pxs[(size_t)i*DIN] = y;
    }
    for (int i = g; i < RC; i += GS) {
        int b = i >> 8, n = i & (NCIT-1);
        float y = c_x_hist[(b*TH + TH-1)*NCIT + n];
        g_yc[i] = y; g_pxc[(size_t)i*DIN] = y;
    }
}

// ---------------- cheb + zgemm phase (software-pipelined staging) ----------------
__device__ __noinline__ void chebz_phase(float* scratch,
        const float* x, const float* lx,
        const float* wc, const float* bc, const float* wz,
        float* xg_out, float* z_out,
        int t0, int tstep, int nt,
        int ymode, const float* yvec) {
    float* swc = scratch;            // 56*64
    float* sb  = swc + 56*64;        // 64
    float* swz = sb + 64;            // 64*64
    float* sxt = swz + 64*64;        // 56*XS
    float* stp = sxt + 56*XS;        // 64*XS
    int tid = threadIdx.x, tx = tid & 31, wid = tid >> 5;
    for (int i = tid; i < 56*64; i += NTHR) swc[i] = wc[i];
    for (int i = tid; i < 64*64; i += NTHR) swz[i] = wz[i];
    if (tid < 64) sb[tid] = bc[tid];
    __syncthreads();
    const int xoff = wid * 4;
    // prefetch first tile's staging
    float4 pv[2];
    if (t0 < nt) {
        long r0 = (long)t0 << 7;
        #pragma unroll
        for (int k = 0; k < 2; k++) {
            int i = tid + k*NTHR;
            if (i < 14*128) {
                int rr = i & 127, c4 = i >> 7;
                long r = r0 + rr;
                pv[k] = (c4 < 7) ? *(const float4*)(x + r*DIN + c4*4)
                                 : *(const float4*)(lx + r*DIN + (c4-7)*4);
            }
        }
    }
    for (int tile = t0; tile < nt; tile += tstep) {
        long r0 = (long)tile << 7;
        // store prefetched staging
        #pragma unroll
        for (int k = 0; k < 2; k++) {
            int i = tid + k*NTHR;
            if (i < 14*128) {
                int rr = i & 127, c4 = i >> 7;
                float4 v = pv[k];
                int chb = (c4 < 7) ? c4*4 : DIN + (c4-7)*4;
                sxt[(chb+0)*XS+rr] = v.x; sxt[(chb+1)*XS+rr] = v.y;
                sxt[(chb+2)*XS+rr] = v.z; sxt[(chb+3)*XS+rr] = v.w;
            }
        }
        if (ymode) {
            __syncthreads();
            if (ymode == 1) {
                for (int rr = wid; rr < 128; rr += 32) {
                    long r = r0 + rr;
                    int b = (int)(r >> 12), node = (int)(r & (NSTA-1));
                    const float* yb = yvec + b*NSTA;
                    int beg = g_Ls_rowptr[node], end = g_Ls_rowptr[node+1];
                    float acc = 0.f;
                    for (int p = beg + tx; p < end; p += 32)
                        acc += g_Ls_vals[p] * yb[g_Ls_cols[p]];
                    #pragma unroll
                    for (int o = 16; o; o >>= 1) acc += __shfl_xor_sync(0xffffffffu, acc, o);
                    if (tx == 0) sxt[DIN*XS + rr] = acc;
                }
            } else {
                for (int rr = wid; rr < 128; rr += 32) {
                    long r = r0 + rr;
                    int b = (int)(r >> 8), node = (int)(r & (NCIT-1));
                    const float* yb = yvec + b*NCIT;
                    const float* Lrow = g_Lc + node*NCIT;
                    float acc = 0.f;
                    for (int j = tx; j < NCIT; j += 32) acc += Lrow[j]*yb[j];
                    #pragma unroll
                    for (int o = 16; o; o >>= 1) acc += __shfl_xor_sync(0xffffffffu, acc, o);
                    if (tx == 0) sxt[DIN*XS + rr] = acc;
                }
            }
        }
        __syncthreads();
        // prefetch NEXT tile (latency hidden behind the GEMMs)
        {
            int tn = tile + tstep;
            if (tn < nt) {
                long rn = (long)tn << 7;
                #pragma unroll
                for (int k = 0; k < 2; k++) {
                    int i = tid + k*NTHR;
                    if (i < 14*128) {
                        int rr = i & 127, c4 = i >> 7;
                        long r = rn + rr;
                        pv[k] = (c4 < 7) ? *(const float4*)(x + r*DIN + c4*4)
                                         : *(const float4*)(lx + r*DIN + (c4-7)*4);
                    }
                }
            }
        }
        // GEMM1: xg = sigm([x|Lx]@Wc + b)
        {
            ull a0[2] = {0,0}, a1[2] = {0,0};
            #pragma unroll 4
            for (int ch = 0; ch < 56; ch++) {
                const float* xr = &sxt[ch*XS + xoff];
                ull xv0 = *(const ull*)(xr);
                ull xv1 = *(const ull*)(xr + 2);
                float2 wv = *(const float2*)&swc[ch*64 + 2*tx];
                ull w0 = splat2(wv.x), w1 = splat2(wv.y);
                fma2(a0[0], xv0, w0); fma2(a0[1], xv1, w0);
                fma2(a1[0], xv0, w1); fma2(a1[1], xv1, w1);
            }
            float b0 = sb[2*tx], b1 = sb[2*tx+1];
            #pragma unroll
            for (int rk = 0; rk < 2; rk++) {
                float2 v0 = unp2(a0[rk]), v1 = unp2(a1[rk]);
                int rr = xoff + rk*2;
                long r = r0 + rr;
                float g00 = sigm(v0.x + b0), g01 = sigm(v1.x + b1);
                float g10 = sigm(v0.y + b0), g11 = sigm(v1.y + b1);
                *(float2*)&xg_out[r*64 + 2*tx]     = make_float2(g00, g01);
                *(float2*)&xg_out[(r+1)*64 + 2*tx] = make_float2(g10, g11);
                stp[(2*tx)*XS + rr]     = g00;
                stp[(2*tx+1)*XS + rr]   = g01;
                stp[(2*tx)*XS + rr+1]   = g10;
                stp[(2*tx+1)*XS + rr+1] = g11;
            }
        }
        __syncthreads();
        // GEMM2: z = xg @ Wz
        {
            ull c0[2] = {0,0}, c1[2] = {0,0};
            #pragma unroll 4
            for (int ch = 0; ch < 64; ch++) {
                const float* xr = &stp[ch*XS + xoff];
                ull xv0 = *(const ull*)(xr);
                ull xv1 = *(const ull*)(xr + 2);
                float2 wv = *(const float2*)&swz[ch*64 + 2*tx];
                ull w0 = splat2(wv.x), w1 = splat2(wv.y);
                fma2(c0[0], xv0, w0); fma2(c0[1], xv1, w0);
                fma2(c1[0], xv0, w1); fma2(c1[1], xv1, w1);
            }
            #pragma unroll
            for (int rk = 0; rk < 2; rk++) {
                float2 v0 = unp2(c0[rk]), v1 = unp2(c1[rk]);
                long r = r0 + xoff + rk*2;
                *(float2*)&z_out[r*64 + 2*tx]     = make_float2(v0.x, v1.x);
                *(float2*)&z_out[(r+1)*64 + 2*tx] = make_float2(v0.y, v1.y);
            }
        }
        __syncthreads();
    }
}

// ---------------- GRU phase (templated NC; xa staging software-pipelined) ----------
template<int NC>
__device__ __noinline__ void gru_phase(
        const float* swi, const float* swh, const float* sbi, const float* sbh,
        float* sxh,
        const float* xa, const float* xg, const float* zo, const float* fb,
        const int* rp, const int* cols, int zo_stride16, int nshift,
        float* h, int t0, int tstep, int nt, int idx,
        const float* fcw, const float* fcb,
        float* ycomp, float* ynext, float* yout, int nnodes, int step) {
    int tid = threadIdx.x, tx = tid & 31, wid = tid >> 5;
    const int xoff = wid * 4;
    // prefetch first tile's xa region
    float4 pvx;
    if (t0 < nt && tid < 7*128) {
        long r0 = (long)t0 << 7;
        int rr = tid & 127, c4 = tid >> 7;
        pvx = *(const float4*)(xa + (r0 + rr)*DIN + c4*4);
    }
    for (int tile = t0; tile < nt; tile += tstep) {
        long r0 = (long)tile << 7;
        // fused-scatter staging (c4 in lanes: coalesced gather, shared CSR rows)
        for (int i = tid; i < 128*16; i += NTHR) {
            int rr = i >> 4, c4 = i & 15;
            long r = r0 + rr;
            int tb = (int)(r >> nshift), node = (int)(r & ((1 << nshift) - 1));
            float4 acc = ((const float4*)fb)[c4];
            int beg = rp[node], end = rp[node+1];
            const float4* src = (const float4*)zo + (size_t)tb * zo_stride16;
            for (int p = beg; p < end; p++) {
                float4 v = src[cols[p]*16 + c4];
                acc.x += v.x; acc.y += v.y; acc.z += v.z; acc.w += v.w;
            }
            float4 xv = ((const float4*)xg)[r*16 + c4];
            acc.x += xv.x; acc.y += xv.y; acc.z += xv.z; acc.w += xv.w;
            int chb = DIN + c4*4;
            sxh[(chb+0)*XS+rr] = acc.x; sxh[(chb+1)*XS+rr] = acc.y;
            sxh[(chb+2)*XS+rr] = acc.z; sxh[(chb+3)*XS+rr] = acc.w;
        }
        // store prefetched xa
        if (tid < 7*128) {
            int rr = tid & 127, c4 = tid >> 7;
            int chb = c4*4;
            sxh[(chb+0)*XS+rr] = pvx.x; sxh[(chb+1)*XS+rr] = pvx.y;
            sxh[(chb+2)*XS+rr] = pvx.z; sxh[(chb+3)*XS+rr] = pvx.w;
        }
        // h staging (rr-major: conflict-free)
        for (int i = tid; i < 16*128; i += NTHR) {
            int rr = i & 127, c4 = i >> 7;
            long r = r0 + rr;
            float4 v = *(const float4*)(h + r*HH + c4*4);
            int chb = DGRU + c4*4;
            sxh[(chb+0)*XS+rr] = v.x; sxh[(chb+1)*XS+rr] = v.y;
            sxh[(chb+2)*XS+rr] = v.z; sxh[(chb+3)*XS+rr] = v.w;
        }
        __syncthreads();
        // prefetch next tile's xa (hidden behind GEMM)
        {
            int tn = tile + tstep;
            if (tn < nt && tid < 7*128) {
                long rn = (long)tn << 7;
                int rr = tid & 127, c4 = tid >> 7;
                pvx = *(const float4*)(xa + (rn + rr)*DIN + c4*4);
            }
        }

        // accumulators: R/Z share (wi+wh summed), N split
        ull aRZ[2*NC][2], aNi[NC][2], aNh[NC][2];
        #pragma unroll
        for (int m = 0; m < 2*NC; m++) { aRZ[m][0] = 0ull; aRZ[m][1] = 0ull; }
        #pragma unroll
        for (int m = 0; m < NC; m++) { aNi[m][0]=aNi[m][1]=0ull; aNh[m][0]=aNh[m][1]=0ull; }

        #pragma unroll 4
        for (int ch = 0; ch < DGRU; ch++) {
            const float* xr = &sxh[ch*XS + xoff];
            ull xv0 = *(const ull*)(xr);
            ull xv1 = *(const ull*)(xr + 2);
            const float* wr = &swi[ch*NG + tx];
            #pragma unroll
            for (int cb = 0; cb < NC; cb++) {
                ull wR = splat2(wr[32*cb]);
                fma2(aRZ[cb][0], xv0, wR); fma2(aRZ[cb][1], xv1, wR);
                ull wZ = splat2(wr[64 + 32*cb]);
                fma2(aRZ[NC+cb][0], xv0, wZ); fma2(aRZ[NC+cb][1], xv1, wZ);
                ull wN = splat2(wr[128 + 32*cb]);
                fma2(aNi[cb][0], xv0, wN); fma2(aNi[cb][1], xv1, wN);
            }
        }
        #pragma unroll 4
        for (int ch = 0; ch < HH; ch++) {
            const float* xr = &sxh[(DGRU+ch)*XS + xoff];
            ull xv0 = *(const ull*)(xr);
            ull xv1 = *(const ull*)(xr + 2);
            const float* wr = &swh[ch*NG + tx];
            #pragma unroll
            for (int cb = 0; cb < NC; cb++) {
                ull wR = splat2(wr[32*cb]);
                fma2(aRZ[cb][0], xv0, wR); fma2(aRZ[cb][1], xv1, wR);
                ull wZ = splat2(wr[64 + 32*cb]);
                fma2(aRZ[NC+cb][0], xv0, wZ); fma2(aRZ[NC+cb][1], xv1, wZ);
                ull wN = splat2(wr[128 + 32*cb]);
                fma2(aNh[cb][0], xv0, wN); fma2(aNh[cb][1], xv1, wN);
            }
        }

        float part[4] = {0.f, 0.f, 0.f, 0.f};
        #pragma unroll
        for (int cb = 0; cb < NC; cb++) {
            int j = cb*32 + tx;
            float bR = sbi[j] + sbh[j];
            float bZ = sbi[j + 64] + sbh[j + 64];
            float biN = sbi[j + 128], bhN = sbh[j + 128];
            int iv = 1 << (j >> 4);
            bool upd = (idx & (iv - 1)) == 0;
            float fw = yout ? fcw[j] : 0.f;
            #pragma unroll
            for (int rk = 0; rk < 2; rk++) {
                float2 vR = unp2(aRZ[cb][rk]);
                float2 vZ = unp2(aRZ[NC+cb][rk]);
                float2 vNi = unp2(aNi[cb][rk]);
                float2 vNh = unp2(aNh[cb][rk]);
                #pragma unroll
                for (int u = 0; u < 2; u++) {
                    int rr = xoff + rk*2 + u;
                    long r = r0 + rr;
                    float avR = u ? vR.y : vR.x;
                    float avZ = u ? vZ.y : vZ.x;
                    float avNi = u ? vNi.y : vNi.x;
                    float avNh = u ? vNh.y : vNh.x;
                    float hold = sxh[(DGRU+j)*XS + rr];
                    float rg = sigm(avR + bR);
                    float z  = sigm(avZ + bZ);
                    float nn = tanhf(avNi + biN + rg*(avNh + bhN));
                    float hf = upd ? ((1.f - z)*nn + z*hold) : hold;
                    if (upd) h[r*HH + j] = hf;
                    part[rk*2 + u] += hf * fw;
                }
            }
        }
        // columns 32..63 untouched when NC==1: contribute their hold value to y
        if (NC == 1 && yout) {
            int j2 = 32 + tx;
            float fw2 = fcw[j2];
            #pragma unroll
            for (int rk = 0; rk < 2; rk++)
                #pragma unroll
                for (int u = 0; u < 2; u++) {
                    int rr = xoff + rk*2 + u;
                    part[rk*2 + u] += sxh[(DGRU+j2)*XS + rr] * fw2;
                }
        }
        if (yout) {
            #pragma unroll
            for (int r4 = 0; r4 < 4; r4++) {
                float v = part[r4];
                v += __shfl_xor_sync(0xffffffffu, v, 16);
                v += __shfl_xor_sync(0xffffffffu, v, 8);
                v += __shfl_xor_sync(0xffffffffu, v, 4);
                v += __shfl_xor_sync(0xffffffffu, v, 2);
                v += __shfl_xor_sync(0xffffffffu, v, 1);
                if (tx == 0) {
                    long r = r0 + xoff + r4;
                    float y = v + fcb[0];
                    ycomp[r] = y;
                    if (ynext) ynext[r*DIN] = y;
                    int b = (int)(r / nnodes), n = (int)(r % nnodes);
                    yout[((size_t)b*TP + step)*nnodes + n] = y;
                }
            }
        }
        __syncthreads();
    }
}

// ================= MEGAKERNEL =================
struct MegaP {
    const float *features, *c_features, *x_hist, *c_x_hist;
    const float *adj_sta, *adj_city, *afc;
    const float *gwi_s, *gwh_s, *gbi_s, *gbh_s;
    const float *gwi_c, *gwh_c, *gbi_c, *gbh_c;
    const float *conv_w, *conv_b, *c_conv_w, *c_conv_b;
    const float *c2s_w, *c2s_b, *s2c_w, *s2c_b;
    const float *fc_w, *fc_b, *c_fc_w, *c_fc_b;
    float *out_s, *out_c;
};

#define SCRATCH_FLOATS (56*64 + 64 + 64*64 + 56*XS + 64*XS + 64)
#define MEGA_SMEM_FLOATS (DGRU*NG + HH*NG + NG + NG + SCRATCH_FLOATS)

__global__ __launch_bounds__(NTHR, 1) void k_mega(MegaP P) {
    extern __shared__ float sm[];
    float* swi = sm;
    float* swh = swi + DGRU*NG;
    float* sbi = swh + HH*NG;
    float* sbh = sbi + NG;
    float* scratch = sbh + NG;

    int bid = blockIdx.x, tid = threadIdx.x;
    bool isC = bid >= NBLK_S;
    int t0 = isC ? (bid - NBLK_S) : bid;
    int tstep = isC ? NBLK_C : NBLK_S;

    // persistent GRU weights
    {
        const float* wi = isC ? P.gwi_c : P.gwi_s;
        const float* wh = isC ? P.gwh_c : P.gwh_s;
        const float* bi = isC ? P.gbi_c : P.gbi_s;
        const float* bh = isC ? P.gbh_c : P.gbh_s;
        for (int i = tid; i < DGRU*NG; i += NTHR) swi[i] = wi[i];
        for (int i = tid; i < HH*NG; i += NTHR) swh[i] = wh[i];
        if (tid < NG) { sbi[tid] = bi[tid]; sbh[tid] = bh[tid]; }
    }

    hist_stage_phase(P.x_hist, P.features, P.c_x_hist, P.c_features);
    buildpx_phase(P.features, P.c_features);
    counts_phase(P.adj_sta, P.afc, P.adj_city);
    gbar();
    scan_phase(scratch);
    gbar();
    fills_phase(P.adj_sta, P.afc, P.adj_city);
    gbar();
    prep2_phase(P.x_hist, P.c_x_hist);
    gbar();
    // history cheb + z
    if (!isC)
        chebz_phase(scratch, g_xs, g_Lxs, P.conv_w, P.conv_b, P.s2c_w,
                    g_xgs, g_zsh, t0, tstep, (THIST*RS) >> 7, 0, nullptr);
    else
        chebz_phase(scratch, g_xc, g_Lxc, P.c_conv_w, P.c_conv_b, P.c2s_w,
                    g_xgc, g_zch, t0, tstep, (THIST*RC) >> 7, 0, nullptr);
    gbar();
    // history GRU (7 steps, scatter fused)
    #pragma unroll 1
    for (int t = 0; t < THIST; t++) {
        int idx = 1 + t;
        bool full = ((idx & 3) == 0);
        if (!isC) {
            if (full)
                gru_phase<2>(swi, swh, sbi, sbh, scratch,
                      g_xs + (size_t)t*RS*DIN, g_xgs + (size_t)t*RS*GF,
                      g_zch + (size_t)t*RC*GF, P.c2s_b,
                      g_afc_rowptr, g_afc_cols, NCIT*16, 12,
                      g_hs, t0, tstep, RS >> 7, idx,
                      nullptr, nullptr, nullptr, nullptr, nullptr, NSTA, 0);
            else
                gru_phase<1>(swi, swh, sbi, sbh, scratch,
                      g_xs + (size_t)t*RS*DIN, g_xgs + (size_t)t*RS*GF,
                      g_zch + (size_t)t*RC*GF, P.c2s_b,
                      g_afc_rowptr, g_afc_cols, NCIT*16, 12,
                      g_hs, t0, tstep, RS >> 7, idx,
                      nullptr, nullptr, nullptr, nullptr, nullptr, NSTA, 0);
        } else {
            if (full)
                gru_phase<2>(swi, swh, sbi, sbh, scratch,
                      g_xc + (size_t)t*RC*DIN, g_xgc + (size_t)t*RC*GF,
                      g_zsh + (size_t)t*RS*GF, P.s2c_b,
                      g_afcT_rowptr, g_afcT_cols, NSTA*16, 8,
                      g_hc, t0, tstep, RC >> 7, idx,
                      nullptr, nullptr, nullptr, nullptr, nullptr, NCIT, 0);
            else
                gru_phase<1>(swi, swh, sbi, sbh, scratch,
                      g_xc + (size_t)t*RC*DIN, g_xgc + (size_t)t*RC*GF,
                      g_zsh + (size_t)t*RS*GF, P.s2c_b,
                      g_afcT_rowptr, g_afcT_cols, NSTA*16, 8,
                      g_hc, t0, tstep, RC >> 7, idx,
                      nullptr, nullptr, nullptr, nullptr, nullptr, NCIT, 0);
        }
        gbar();
    }
    // pred loop (24 steps, 2 phases each)
    #pragma unroll 1
    for (int s = 0; s < TP; s++) {
        int idx = TH + s;
        bool full = ((idx & 3) == 0);
        float* pxs_s  = g_pxs  + (size_t)s*SPS;
        float* pLxs_s = g_pLxs + (size_t)s*SPS;
        float* pxc_s  = g_pxc  + (size_t)s*SPC;
        float* pLxc_s = g_pLxc + (size_t)s*SPC;
        if (!isC)
            chebz_phase(scratch, pxs_s, pLxs_s, P.conv_w, P.conv_b, P.s2c_w,
                        g_xgs, g_zsh, t0, tstep, RS >> 7, 1, g_ys);
        else
            chebz_phase(scratch, pxc_s, pLxc_s, P.c_conv_w, P.c_conv_b, P.c2s_w,
                        g_xgc, g_zch, t0, tstep, RC >> 7, 2, g_yc);
        gbar();
        float* ynext_s = (s + 1 < TP) ? (g_pxs + (size_t)(s+1)*SPS) : nullptr;
        float* ynext_c = (s + 1 < TP) ? (g_pxc + (size_t)(s+1)*SPC) : nullptr;
        if (!isC) {
            if (full)
                gru_phase<2>(swi, swh, sbi, sbh, scratch,
                      pxs_s, g_xgs, g_zch, P.c2s_b,
                      g_afc_rowptr, g_afc_cols, NCIT*16, 12,
                      g_hs, t0, tstep, RS >> 7, idx,
                      P.fc_w, P.fc_b, g_ys, ynext_s, P.out_s, NSTA, s);
            else
                gru_phase<1>(swi, swh, sbi, sbh, scratch,
                      pxs_s, g_xgs, g_zch, P.c2s_b,
                      g_afc_rowptr, g_afc_cols, NCIT*16, 12,
                      g_hs, t0, tstep, RS >> 7, idx,
                      P.fc_w, P.fc_b, g_ys, ynext_s, P.out_s, NSTA, s);
        } else {
            if (full)
                gru_phase<2>(swi, swh, sbi, sbh, scratch,
                      pxc_s, g_xgc, g_zsh, P.s2c_b,
                      g_afcT_rowptr, g_afcT_cols, NSTA*16, 8,
                      g_hc, t0, tstep, RC >> 7, idx,
                      P.c_fc_w, P.c_fc_b, g_yc, ynext_c, P.out_c, NCIT, s);
            else
                gru_phase<1>(swi, swh, sbi, sbh, scratch,
                      pxc_s, g_xgc, g_zsh, P.s2c_b,
                      g_afcT_rowptr, g_afcT_cols, NSTA*16, 8,
                      g_hc, t0, tstep, RC >> 7, idx,
                      P.c_fc_w, P.c_fc_b, g_yc, ynext_c, P.out_c, NCIT, s);
        }
        gbar();
    }
}

// ---------------- host ----------------
extern "C" void kernel_launch(void* const* d_in, const int* in_sizes, int n_in,
                              void* d_out, int out_size) {
    MegaP P;
    P.x_hist     = (const float*)d_in[0];
    P.features   = (const float*)d_in[1];
    P.c_x_hist   = (const float*)d_in[2];
    P.c_features = (const float*)d_in[3];
    P.adj_sta    = (const float*)d_in[4];
    P.adj_city   = (const float*)d_in[5];
    P.afc        = (const float*)d_in[6];
    P.conv_w     = (const float*)d_in[7];
    P.conv_b     = (const float*)d_in[8];
    P.c_conv_w   = (const float*)d_in[9];
    P.c_conv_b   = (const float*)d_in[10];
    P.gwi_s      = (const float*)d_in[11];
    P.gwh_s      = (const float*)d_in[12];
    P.gbi_s      = (const float*)d_in[13];
    P.gbh_s      = (const float*)d_in[14];
    P.gwi_c      = (const float*)d_in[15];
    P.gwh_c      = (const float*)d_in[16];
    P.gbi_c      = (const float*)d_in[17];
    P.gbh_c      = (const float*)d_in[18];
    P.fc_w       = (const float*)d_in[19];
    P.fc_b       = (const float*)d_in[20];
    P.c_fc_w     = (const float*)d_in[21];
    P.c_fc_b     = (const float*)d_in[22];
    P.c2s_w      = (const float*)d_in[23];
    P.c2s_b      = (const float*)d_in[24];
    P.s2c_w      = (const float*)d_in[25];
    P.s2c_b      = (const float*)d_in[26];
    P.out_s = (float*)d_out;
    P.out_c = P.out_s + (size_t)NB * TP * NSTA;

    (void)in_sizes; (void)n_in; (void)out_size;

    const int mega_smem = MEGA_SMEM_FLOATS * (int)sizeof(float);
    cudaFuncSetAttribute(k_mega, cudaFuncAttributeMaxDynamicSharedMemorySize, mega_smem);
    k_mega<<<NBLK, NTHR, mega_smem>>>(P);
}

// round 16
// speedup vs baseline: 1.0591x; 1.0591x over previous
#include <cuda_runtime.h>
#include <math.h>

#define NSTA 4096
#define NCIT 256
#define NB 8
#define TH 8
#define TP 24
#define TT 32
#define DIN 28
#define DM 27
#define GF 64
#define HH 64
#define NG 192
#define DGRU 92
#define THIST 7
#define NNZMAX (1<<20)

#define NBLK   148
#define NBLK_S 128
#define NBLK_C 20
#define NTHR   1024
#define XS     130     // smem tile row-stride

#define SPS (NB*NSTA*DIN)
#define SPC (NB*NCIT*DIN)
#define RS  (NB*NSTA)
#define RC  (NB*NCIT)

typedef unsigned long long ull;

// ---------------- static device scratch ----------------
__device__ float g_dinv_s[NSTA];
__device__ int   g_cnt_s[NSTA];
__device__ int   g_Ls_rowptr[NSTA+1];
__device__ int   g_Ls_cols[NNZMAX];
__device__ float g_Ls_vals[NNZMAX];

__device__ int   g_cnt_afc[NSTA];
__device__ int   g_afc_rowptr[NSTA+1];
__device__ int   g_afc_cols[NNZMAX];

__device__ int   g_cnt_afcT[NCIT];
__device__ int   g_afcT_rowptr[NCIT+1];
__device__ int   g_afcT_cols[NNZMAX];

__device__ float g_dinv_c[NCIT];
__device__ int   g_cnt_c[NCIT];
__device__ float g_Lc[NCIT*NCIT];

// history buffers
__device__ float g_xs [THIST*RS*DIN];
__device__ float g_Lxs[THIST*RS*DIN];
__device__ float g_xgs[THIST*RS*GF];
__device__ float g_zsh[THIST*RS*GF];

__device__ float g_xc [THIST*RC*DIN];
__device__ float g_Lxc[THIST*RC*DIN];
__device__ float g_xgc[THIST*RC*GF];
__device__ float g_zch[THIST*RC*GF];

// pred precomputed x / Lx (all 24 steps)
__device__ float g_pxs [TP*SPS];
__device__ float g_pLxs[TP*SPS];
__device__ float g_pxc [TP*SPC];
__device__ float g_pLxc[TP*SPC];

__device__ float g_hs[RS*HH];
__device__ float g_hc[RC*HH];
__device__ float g_ys[RS];
__device__ float g_yc[RC];

// grid barrier state
__device__ unsigned g_bar_cnt = 0;
__device__ volatile unsigned g_bar_gen = 0;

// ---------------- helpers ----------------
__device__ __forceinline__ ull splat2(float w) {
    ull r;
    asm("mov.b64 %0, {%1, %1};" : "=l"(r) : "f"(w));
    return r;
}
__device__ __forceinline__ void fma2(ull& a, ull x, ull w) {
    asm("fma.rn.f32x2 %0, %1, %2, %0;" : "+l"(a) : "l"(x), "l"(w));
}
__device__ __forceinline__ float2 unp2(ull v) {
    float2 f;
    asm("mov.b64 {%0, %1}, %2;" : "=f"(f.x), "=f"(f.y) : "l"(v));
    return f;
}
__device__ __forceinline__ float sigm(float x) { return 1.f / (1.f + __expf(-x)); }

__device__ __forceinline__ void gbar() {
    __syncthreads();
    if (threadIdx.x == 0) {
        unsigned gen = g_bar_gen;
        __threadfence();
        unsigned t = atomicAdd(&g_bar_cnt, 1);
        if (t == (unsigned)(NBLK - 1)) {
            g_bar_cnt = 0;
            __threadfence();
            g_bar_gen = gen + 1;
        } else {
            while (g_bar_gen == gen) { __nanosleep(64); }
        }
    }
    __syncthreads();
    __threadfence();
}

__device__ __forceinline__ int wredi(int c) {
    #pragma unroll
    for (int o = 16; o; o >>= 1) c += __shfl_xor_sync(0xffffffffu, c, o);
    return c;
}

// ---------------- preproc device functions ----------------
__device__ __noinline__ void counts_phase(const float* adj_sta, const float* afc,
                                          const float* adj_city) {
    int gw = (blockIdx.x*NTHR + threadIdx.x) >> 5;
    int lane = threadIdx.x & 31;
    const int NW = NBLK*(NTHR/32);
    for (int m = gw; m < NSTA; m += NW) {
        int c = 0;
        const float* row = adj_sta + (size_t)m*NSTA;
        for (int j = lane; j < NSTA; j += 32) c += (row[j] != 0.f && j != m);
        c = wredi(c);
        if (lane == 0) { g_cnt_s[m] = c; g_dinv_s[m] = c > 0 ? rsqrtf((float)c) : 0.f; }
    }
    for (int m = gw; m < NSTA; m += NW) {
        int c = 0;
        const float* row = afc + (size_t)m*NCIT;
        for (int j = lane; j < NCIT; j += 32) c += (row[j] != 0.f);
        c = wredi(c);
        if (lane == 0) g_cnt_afc[m] = c;
    }
    for (int cc = gw; cc < NCIT; cc += NW) {
        int c = 0;
        for (int s = lane; s < NSTA; s += 32) c += (afc[(size_t)s*NCIT + cc] != 0.f);
        c = wredi(c);
        if (lane == 0) g_cnt_afcT[cc] = c;
    }
    for (int m = gw; m < NCIT; m += NW) {
        int c = 0;
        const float* row = adj_city + (size_t)m*NCIT;
        for (int j = lane; j < NCIT; j += 32) c += (row[j] != 0.f && j != m);
        c = wredi(c);
        if (lane == 0) { g_cnt_c[m] = c; g_dinv_c[m] = c > 0 ? rsqrtf((float)c) : 0.f; }
    }
}

__device__ __noinline__ void scan_phase(float* scratch) {
    if (blockIdx.x >= 3) return;
    int* s = (int*)scratch;
    const int* cnt; int* rp; int n;
    if (blockIdx.x == 0) { cnt = g_cnt_s; rp = g_Ls_rowptr; n = NSTA; }
    else if (blockIdx.x == 1) { cnt = g_cnt_afc; rp = g_afc_rowptr; n = NSTA; }
    else { cnt = g_cnt_afcT; rp = g_afcT_rowptr; n = NCIT; }
    int tid = threadIdx.x;
    int per = (n + NTHR - 1) / NTHR;
    int base = tid * per;
    int loc = 0;
    for (int i = 0; i < per; i++) if (base + i < n) loc += cnt[base + i];
    s[tid] = loc; __syncthreads();
    for (int off = 1; off < NTHR; off <<= 1) {
        int v = (tid >= off) ? s[tid - off] : 0;
        __syncthreads();
        s[tid] += v;
        __syncthreads();
    }
    int a = tid ? s[tid - 1] : 0;
    for (int i = 0; i < per; i++)
        if (base + i < n) { rp[base + i] = a; a += cnt[base + i]; }
    if (tid == NTHR - 1) rp[n] = a;
}

__device__ void fill_csr_row(const float* __restrict__ mat, const int* __restrict__ rowptr,
                             int* __restrict__ cols, float* __restrict__ vals,
                             const float* __restrict__ dinv,
                             int ncols, int excl, int m) {
    int lane = threadIdx.x & 31;
    int pos = rowptr[m];
    float dm = dinv ? dinv[m] : 0.f;
    for (int base = 0; base < ncols; base += 32) {
        int j = base + lane;
        bool p = (j < ncols) && (mat[(size_t)m*ncols + j] != 0.f) && !(excl && j == m);
        unsigned msk = __ballot_sync(0xffffffffu, p);
        if (p) {
            int off = __popc(msk & ((1u << lane) - 1u));
            cols[pos + off] = j;
            if (vals) vals[pos + off] = -dm * dinv[j];
        }
        pos += __popc(msk);
    }
}

__device__ void fill_csrT_col(const float* __restrict__ mat, const int* __restrict__ rowptr,
                              int* __restrict__ cols, int nrows, int ncols, int c) {
    int lane = threadIdx.x & 31;
    int pos = rowptr[c];
    for (int base = 0; base < nrows; base += 32) {
        int s = base + lane;
        bool p = (s < nrows) && (mat[(size_t)s*ncols + c] != 0.f);
        unsigned msk = __ballot_sync(0xffffffffu, p);
        if (p) cols[pos + __popc(msk & ((1u << lane) - 1u))] = s;
        pos += __popc(msk);
    }
}

__device__ __noinline__ void fills_phase(const float* adj_sta, const float* afc,
                                         const float* adj_city) {
    int gw = (blockIdx.x*NTHR + threadIdx.x) >> 5;
    const int NW = NBLK*(NTHR/32);
    for (int m = gw; m < NSTA; m += NW)
        fill_csr_row(adj_sta, g_Ls_rowptr, g_Ls_cols, g_Ls_vals, g_dinv_s, NSTA, 1, m);
    for (int m = gw; m < NSTA; m += NW)
        fill_csr_row(afc, g_afc_rowptr, g_afc_cols, nullptr, nullptr, NCIT, 0, m);
    for (int c = gw; c < NCIT; c += NW)
        fill_csrT_col(afc, g_afcT_rowptr, g_afcT_cols, NSTA, NCIT, c);
    int g = blockIdx.x*NTHR + threadIdx.x;
    for (int i = g; i < NCIT*NCIT; i += NBLK*NTHR) {
        int m = i >> 8, n = i & 255;
        float v = 0.f;
        if (n != m && adj_city[i] != 0.f) v = -g_dinv_c[m]*g_dinv_c[n];
        g_Lc[i] = v;
    }
}

__device__ __noinline__ void hist_stage_phase(const float* xh_s, const float* ft_s,
                                              const float* xh_c, const float* ft_c) {
    int g = blockIdx.x*NTHR + threadIdx.x;
    const int GS = NBLK*NTHR;
    const int nS = THIST*RS*DIN;
    for (int i = g; i < nS; i += GS) {
        int ch = i % DIN; int r = i / DIN; int n = r % NSTA; int tb = r / NSTA;
        int b = tb % NB; int t = tb / NB;
        g_xs[i] = (ch == 0) ? xh_s[(b*TH + t)*NSTA + n]
                            : ft_s[((size_t)(b*TT + (t+1))*NSTA + n)*DM + (ch-1)];
    }
    const int nC = THIST*RC*DIN;
    for (int i = g; i < nC; i += GS) {
        int ch = i % DIN; int r = i / DIN; int n = r % NCIT; int tb = r / NCIT;
        int b = tb % NB; int t = tb / NB;
        g_xc[i] = (ch == 0) ? xh_c[(b*TH + t)*NCIT + n]
                            : ft_c[((size_t)(b*TT + (t+1))*NCIT + n)*DM + (ch-1)];
    }
}

__device__ __noinline__ void buildpx_phase(const float* ft_s, const float* ft_c) {
    int g = blockIdx.x*NTHR + threadIdx.x;
    const int GS = NBLK*NTHR;
    const int totS = TP*NB*NSTA*DM;
    for (int i = g; i < totS; i += GS) {
        int ch = i % DM; int q = i / DM;
        int n = q & (NSTA-1); q >>= 12;
        int b = q & 7; int s = q >> 3;
        g_pxs[((size_t)(s*NB+b)*NSTA + n)*DIN + 1 + ch] =
            ft_s[(((size_t)b*TT + TH + s)*NSTA + n)*DM + ch];
    }
    const int totC = TP*NB*NCIT*DM;
    for (int i = g; i < totC; i += GS) {
        int ch = i % DM; int q = i / DM;
        int n = q & (NCIT-1); q >>= 8;
        int b = q & 7; int s = q >> 3;
        g_pxc[((size_t)(s*NB+b)*NCIT + n)*DIN + 1 + ch] =
            ft_c[(((size_t)b*TT + TH + s)*NCIT + n)*DM + ch];
    }
}

// histL + pred feature pLx + h/y init
__device__ __noinline__ void prep2_phase(const float* x_hist, const float* c_x_hist) {
    int gw = (blockIdx.x*NTHR + threadIdx.x) >> 5;
    int lane = threadIdx.x & 31;
    const int NW = NBLK*(NTHR/32);
    const int tasks = NSTA*THIST*NB;
    for (int t = gw; t < tasks; t += NW) {
        int m = t / (THIST*NB);
        int tb = t % (THIST*NB);
        int beg = g_Ls_rowptr[m], end = g_Ls_rowptr[m+1];
        const float* xb = g_xs + (size_t)tb*NSTA*DIN;
        if (lane < DIN) {
            float acc = 0.f;
            for (int p = beg; p < end; p++)
                acc += g_Ls_vals[p] * xb[g_Ls_cols[p]*DIN + lane];
            g_Lxs[((size_t)tb*NSTA + m)*DIN + lane] = acc;
        }
    }
    const int ptasks = TP*RS;
    for (int t = gw; t < ptasks; t += NW) {
        int n = t & (NSTA-1); int q = t >> 12;
        int b = q & 7; int s = q >> 3;
        int beg = g_Ls_rowptr[n], end = g_Ls_rowptr[n+1];
        const float* xb = g_pxs + (size_t)(s*NB+b)*NSTA*DIN;
        if (lane < DM) {
            float acc = 0.f;
            for (int p = beg; p < end; p++)
                acc += g_Ls_vals[p] * xb[g_Ls_cols[p]*DIN + 1 + lane];
            g_pLxs[((size_t)(s*NB+b)*NSTA + n)*DIN + 1 + lane] = acc;
        }
    }
    int g = blockIdx.x*NTHR + threadIdx.x;
    const int GS = NBLK*NTHR;
    for (int i = g; i < THIST*RC*DIN; i += GS) {
        int ch = i % DIN; int r = i / DIN; int m = r % NCIT; int tb = r / NCIT;
        const float* xb = g_xc + (size_t)tb*NCIT*DIN;
        float acc = 0.f;
        for (int j = 0; j < NCIT; j++) acc += g_Lc[m*NCIT + j]*xb[j*DIN + ch];
        g_Lxc[i] = acc;
    }
    for (int i = g; i < TP*RC*DM; i += GS) {
        int ch = i % DM; int q = i / DM;
        int n = q & (NCIT-1); q >>= 8;
        int b = q & 7; int s = q >> 3;
        const float* xb = g_pxc + (size_t)(s*NB+b)*NCIT*DIN;
        float acc = 0.f;
        for (int j = 0; j < NCIT; j++) acc += g_Lc[n*NCIT + j]*xb[j*DIN + 1 + ch];
        g_pLxc[((size_t)(s*NB+b)*NCIT + n)*DIN + 1 + ch] = acc;
    }
    for (int i = g; i < RS*HH; i += GS) g_hs[i] = 0.f;
    for (int i = g; i < RC*HH; i += GS) g_hc[i] = 0.f;
    for (int i = g; i < RS; i += GS) {
        int b = i >> 12, n = i & (NSTA-1);
        float y = x_hist[(b*TH + TH-1)*NSTA + n];
        g_ys[i] = y; g_pxs[(size_t)i*DIN] = y;
    }
    for (int i = g; i < RC; i += GS) {
        int b = i >> 8, n = i & (NCIT-1);
        float y = c_x_hist[(b*TH + TH-1)*NCIT + n];
        g_yc[i] = y; g_pxc[(size_t)i*DIN] = y;
    }
}

// ---------------- cheb + zgemm phase (128-row tiles, 4 rows/warp, 32 warps) ----------------
__device__ __noinline__ void chebz_phase(float* scratch,
        const float* x, const float* lx,
        const float* wc, const float* bc, const float* wz,
        float* xg_out, float* z_out,
        int t0, int tstep, int nt,
        int ymode, const float* yvec) {
    float* swc = scratch;            // 56*64
    float* sb  = swc + 56*64;        // 64
    float* swz = sb + 64;            // 64*64
    float* sxt = swz + 64*64;        // 56*XS
    float* stp = sxt + 56*XS;        // 64*XS
    int tid = threadIdx.x, tx = tid & 31, wid = tid >> 5;
    for (int i = tid; i < 56*64; i += NTHR) swc[i] = wc[i];
    for (int i = tid; i < 64*64; i += NTHR) swz[i] = wz[i];
    if (tid < 64) sb[tid] = bc[tid];
    __syncthreads();
    const int xoff = wid * 4;
    for (int tile = t0; tile < nt; tile += tstep) {
        long r0 = (long)tile << 7;
        for (int i = tid; i < 14*128; i += NTHR) {
            int rr = i & 127, c4 = i >> 7;
            long r = r0 + rr;
            float4 v; int chb;
            if (c4 < 7) { v = *(const float4*)(x + r*DIN + c4*4); chb = c4*4; }
            else { v = *(const float4*)(lx + r*DIN + (c4-7)*4); chb = DIN + (c4-7)*4; }
            sxt[(chb+0)*XS+rr] = v.x; sxt[(chb+1)*XS+rr] = v.y;
            sxt[(chb+2)*XS+rr] = v.z; sxt[(chb+3)*XS+rr] = v.w;
        }
        if (ymode) {
            __syncthreads();
            if (ymode == 1) {
                for (int rr = wid; rr < 128; rr += 32) {
                    long r = r0 + rr;
                    int b = (int)(r >> 12), node = (int)(r & (NSTA-1));
                    const float* yb = yvec + b*NSTA;
                    int beg = g_Ls_rowptr[node], end = g_Ls_rowptr[node+1];
                    float acc = 0.f;
                    for (int p = beg + tx; p < end; p += 32)
                        acc += g_Ls_vals[p] * yb[g_Ls_cols[p]];
                    #pragma unroll
                    for (int o = 16; o; o >>= 1) acc += __shfl_xor_sync(0xffffffffu, acc, o);
                    if (tx == 0) sxt[DIN*XS + rr] = acc;
                }
            } else {
                for (int rr = wid; rr < 128; rr += 32) {
                    long r = r0 + rr;
                    int b = (int)(r >> 8), node = (int)(r & (NCIT-1));
                    const float* yb = yvec + b*NCIT;
                    const float* Lrow = g_Lc + node*NCIT;
                    float acc = 0.f;
                    for (int j = tx; j < NCIT; j += 32) acc += Lrow[j]*yb[j];
                    #pragma unroll
                    for (int o = 16; o; o >>= 1) acc += __shfl_xor_sync(0xffffffffu, acc, o);
                    if (tx == 0) sxt[DIN*XS + rr] = acc;
                }
            }
        }
        __syncthreads();
        // GEMM1: xg = sigm([x|Lx]@Wc + b)
        {
            ull a0[2] = {0,0}, a1[2] = {0,0};
            #pragma unroll 4
            for (int ch = 0; ch < 56; ch++) {
                const float* xr = &sxt[ch*XS + xoff];
                ull xv0 = *(const ull*)(xr);
                ull xv1 = *(const ull*)(xr + 2);
                float2 wv = *(const float2*)&swc[ch*64 + 2*tx];
                ull w0 = splat2(wv.x), w1 = splat2(wv.y);
                fma2(a0[0], xv0, w0); fma2(a0[1], xv1, w0);
                fma2(a1[0], xv0, w1); fma2(a1[1], xv1, w1);
            }
            float b0 = sb[2*tx], b1 = sb[2*tx+1];
            #pragma unroll
            for (int rk = 0; rk < 2; rk++) {
                float2 v0 = unp2(a0[rk]), v1 = unp2(a1[rk]);
                int rr = xoff + rk*2;
                long r = r0 + rr;
                float g00 = sigm(v0.x + b0), g01 = sigm(v1.x + b1);
                float g10 = sigm(v0.y + b0), g11 = sigm(v1.y + b1);
                *(float2*)&xg_out[r*64 + 2*tx]     = make_float2(g00, g01);
                *(float2*)&xg_out[(r+1)*64 + 2*tx] = make_float2(g10, g11);
                stp[(2*tx)*XS + rr]     = g00;
                stp[(2*tx+1)*XS + rr]   = g01;
                stp[(2*tx)*XS + rr+1]   = g10;
                stp[(2*tx+1)*XS + rr+1] = g11;
            }
        }
        __syncthreads();
        // GEMM2: z = xg @ Wz
        {
            ull c0[2] = {0,0}, c1[2] = {0,0};
            #pragma unroll 4
            for (int ch = 0; ch < 64; ch++) {
                const float* xr = &stp[ch*XS + xoff];
                ull xv0 = *(const ull*)(xr);
                ull xv1 = *(const ull*)(xr + 2);
                float2 wv = *(const float2*)&swz[ch*64 + 2*tx];
                ull w0 = splat2(wv.x), w1 = splat2(wv.y);
                fma2(c0[0], xv0, w0); fma2(c0[1], xv1, w0);
                fma2(c1[0], xv0, w1); fma2(c1[1], xv1, w1);
            }
            #pragma unroll
            for (int rk = 0; rk < 2; rk++) {
                float2 v0 = unp2(c0[rk]), v1 = unp2(c1[rk]);
                long r = r0 + xoff + rk*2;
                *(float2*)&z_out[r*64 + 2*tx]     = make_float2(v0.x, v1.x);
                *(float2*)&z_out[(r+1)*64 + 2*tx] = make_float2(v0.y, v1.y);
            }
        }
        __syncthreads();
    }
}

// ---------------- shared staging for GRU ----------------
__device__ __forceinline__ void gru_stage(float* sxh,
        const float* xa, const float* xg, const float* zo, const float* fb,
        const int* rp, const int* cols, int zo_stride16, int nshift,
        const float* h, long r0) {
    int tid = threadIdx.x;
    // fused-scatter staging (c4 in lanes: coalesced gather, shared CSR rows)
    for (int i = tid; i < 128*16; i += NTHR) {
        int rr = i >> 4, c4 = i & 15;
        long r = r0 + rr;
        int tb = (int)(r >> nshift), node = (int)(r & ((1 << nshift) - 1));
        float4 acc = ((const float4*)fb)[c4];
        int beg = rp[node], end = rp[node+1];
        const float4* src = (const float4*)zo + (size_t)tb * zo_stride16;
        for (int p = beg; p < end; p++) {
            float4 v = src[cols[p]*16 + c4];
            acc.x += v.x; acc.y += v.y; acc.z += v.z; acc.w += v.w;
        }
        float4 xv = ((const float4*)xg)[r*16 + c4];
        acc.x += xv.x; acc.y += xv.y; acc.z += xv.z; acc.w += xv.w;
        int chb = DIN + c4*4;
        sxh[(chb+0)*XS+rr] = acc.x; sxh[(chb+1)*XS+rr] = acc.y;
        sxh[(chb+2)*XS+rr] = acc.z; sxh[(chb+3)*XS+rr] = acc.w;
    }
    // xa + h staging (rr-major: conflict-free)
    for (int i = tid; i < 23*128; i += NTHR) {
        int rr = i & 127, c4 = i >> 7;
        long r = r0 + rr;
        float4 v; int chb;
        if (c4 < 7) { v = *(const float4*)(xa + r*DIN + c4*4); chb = c4*4; }
        else { v = *(const float4*)(h + r*HH + (c4-7)*4); chb = DGRU + (c4-7)*4; }
        sxh[(chb+0)*XS+rr] = v.x; sxh[(chb+1)*XS+rr] = v.y;
        sxh[(chb+2)*XS+rr] = v.z; sxh[(chb+3)*XS+rr] = v.w;
    }
}

// ---------------- GRU phase (templated on active column blocks NC) ----------------
// NC=1: h-columns 0..31 can update (idx%2==0, idx%4!=0); NC=2: all 64.
template<int NC>
__device__ __noinline__ void gru_phase(
        const float* swi, const float* swh, const float* sbi, const float* sbh,
        float* sxh,
        const float* xa, const float* xg, const float* zo, const float* fb,
        const int* rp, const int* cols, int zo_stride16, int nshift,
        float* h, int t0, int tstep, int nt, int idx,
        const float* fcw, const float* fcb,
        float* ycomp, float* ynext, float* yout, int nnodes, int step) {
    int tid = threadIdx.x, tx = tid & 31, wid = tid >> 5;
    const int xoff = wid * 4;
    for (int tile = t0; tile < nt; tile += tstep) {
        long r0 = (long)tile << 7;
        gru_stage(sxh, xa, xg, zo, fb, rp, cols, zo_stride16, nshift, h, r0);
        __syncthreads();

        // accumulators: R/Z share (wi+wh summed), N split
        ull aRZ[2*NC][2], aNi[NC][2], aNh[NC][2];
        #pragma unroll
        for (int m = 0; m < 2*NC; m++) { aRZ[m][0] = 0ull; aRZ[m][1] = 0ull; }
        #pragma unroll
        for (int m = 0; m < NC; m++) { aNi[m][0]=aNi[m][1]=0ull; aNh[m][0]=aNh[m][1]=0ull; }

        #pragma unroll 4
        for (int ch = 0; ch < DGRU; ch++) {
            const float* xr = &sxh[ch*XS + xoff];
            ull xv0 = *(const ull*)(xr);
            ull xv1 = *(const ull*)(xr + 2);
            const float* wr = &swi[ch*NG + tx];
            #pragma unroll
            for (int cb = 0; cb < NC; cb++) {
                ull wR = splat2(wr[32*cb]);
                fma2(aRZ[cb][0], xv0, wR); fma2(aRZ[cb][1], xv1, wR);
                ull wZ = splat2(wr[64 + 32*cb]);
                fma2(aRZ[NC+cb][0], xv0, wZ); fma2(aRZ[NC+cb][1], xv1, wZ);
                ull wN = splat2(wr[128 + 32*cb]);
                fma2(aNi[cb][0], xv0, wN); fma2(aNi[cb][1], xv1, wN);
            }
        }
        #pragma unroll 4
        for (int ch = 0; ch < HH; ch++) {
            const float* xr = &sxh[(DGRU+ch)*XS + xoff];
            ull xv0 = *(const ull*)(xr);
            ull xv1 = *(const ull*)(xr + 2);
            const float* wr = &swh[ch*NG + tx];
            #pragma unroll
            for (int cb = 0; cb < NC; cb++) {
                ull wR = splat2(wr[32*cb]);
                fma2(aRZ[cb][0], xv0, wR); fma2(aRZ[cb][1], xv1, wR);
                ull wZ = splat2(wr[64 + 32*cb]);
                fma2(aRZ[NC+cb][0], xv0, wZ); fma2(aRZ[NC+cb][1], xv1, wZ);
                ull wN = splat2(wr[128 + 32*cb]);
                fma2(aNh[cb][0], xv0, wN); fma2(aNh[cb][1], xv1, wN);
            }
        }

        float part[4] = {0.f, 0.f, 0.f, 0.f};
        #pragma unroll
        for (int cb = 0; cb < NC; cb++) {
            int j = cb*32 + tx;
            float bR = sbi[j] + sbh[j];
            float bZ = sbi[j + 64] + sbh[j + 64];
            float biN = sbi[j + 128], bhN = sbh[j + 128];
            int iv = 1 << (j >> 4);
            bool upd = (idx & (iv - 1)) == 0;
            float fw = yout ? fcw[j] : 0.f;
            #pragma unroll
            for (int rk = 0; rk < 2; rk++) {
                float2 vR = unp2(aRZ[cb][rk]);
                float2 vZ = unp2(aRZ[NC+cb][rk]);
                float2 vNi = unp2(aNi[cb][rk]);
                float2 vNh = unp2(aNh[cb][rk]);
                #pragma unroll
                for (int u = 0; u < 2; u++) {
                    int rr = xoff + rk*2 + u;
                    long r = r0 + rr;
                    float avR = u ? vR.y : vR.x;
                    float avZ = u ? vZ.y : vZ.x;
                    float avNi = u ? vNi.y : vNi.x;
                    float avNh = u ? vNh.y : vNh.x;
                    float hold = sxh[(DGRU+j)*XS + rr];
                    float rg = sigm(avR + bR);
                    float z  = sigm(avZ + bZ);
                    float nn = tanhf(avNi + biN + rg*(avNh + bhN));
                    float hf = upd ? ((1.f - z)*nn + z*hold) : hold;
                    if (upd) h[r*HH + j] = hf;
                    part[rk*2 + u] += hf * fw;
                }
            }
        }
        // columns 32..63 untouched when NC==1: contribute their hold value to y
        if (NC == 1 && yout) {
            int j2 = 32 + tx;
            float fw2 = fcw[j2];
            #pragma unroll
            for (int rk = 0; rk < 2; rk++)
                #pragma unroll
                for (int u = 0; u < 2; u++) {
                    int rr = xoff + rk*2 + u;
                    part[rk*2 + u] += sxh[(DGRU+j2)*XS + rr] * fw2;
                }
        }
        if (yout) {
            #pragma unroll
            for (int r4 = 0; r4 < 4; r4++) {
                float v = part[r4];
                v += __shfl_xor_sync(0xffffffffu, v, 16);
                v += __shfl_xor_sync(0xffffffffu, v, 8);
                v += __shfl_xor_sync(0xffffffffu, v, 4);
                v += __shfl_xor_sync(0xffffffffu, v, 2);
                v += __shfl_xor_sync(0xffffffffu, v, 1);
                if (tx == 0) {
                    long r = r0 + xoff + r4;
                    float y = v + fcb[0];
                    ycomp[r] = y;
                    if (ynext) ynext[r*DIN] = y;
                    int b = (int)(r / nnodes), n = (int)(r % nnodes);
                    yout[((size_t)b*TP + step)*nnodes + n] = y;
                }
            }
        }
        __syncthreads();
    }
}

// ---------------- GRU phase HALF: odd idx — only columns 0..15 update -------------
// lane = 16*hh2 + jh: column jh (0..15), rows xoff + hh2*2 + {0,1}
__device__ __noinline__ void gruh_phase(
        const float* swi, const float* swh, const float* sbi, const float* sbh,
        float* sxh,
        const float* xa, const float* xg, const float* zo, const float* fb,
        const int* rp, const int* cols, int zo_stride16, int nshift,
        float* h, int t0, int tstep, int nt,
        const float* fcw, const float* fcb,
        float* ycomp, float* ynext, float* yout, int nnodes, int step) {
    int tid = threadIdx.x, tx = tid & 31, wid = tid >> 5;
    const int xoff = wid * 4;
    int jh = tx & 15;
    int hh2 = tx >> 4;
    const int roff = xoff + hh2*2;
    for (int tile = t0; tile < nt; tile += tstep) {
        long r0 = (long)tile << 7;
        gru_stage(sxh, xa, xg, zo, fb, rp, cols, zo_stride16, nshift, h, r0);
        __syncthreads();

        ull aR = 0ull, aZ = 0ull, aNi = 0ull, aNh = 0ull;
        #pragma unroll 4
        for (int ch = 0; ch < DGRU; ch++) {
            ull xv = *(const ull*)&sxh[ch*XS + roff];
            const float* wr = &swi[ch*NG + jh];
            fma2(aR,  xv, splat2(wr[0]));
            fma2(aZ,  xv, splat2(wr[64]));
            fma2(aNi, xv, splat2(wr[128]));
        }
        #pragma unroll 4
        for (int ch = 0; ch < HH; ch++) {
            ull xv = *(const ull*)&sxh[(DGRU+ch)*XS + roff];
            const float* wr = &swh[ch*NG + jh];
            fma2(aR,  xv, splat2(wr[0]));
            fma2(aZ,  xv, splat2(wr[64]));
            fma2(aNh, xv, splat2(wr[128]));
        }

        int j = jh;
        float bR = sbi[j] + sbh[j];
        float bZ = sbi[j + 64] + sbh[j + 64];
        float biN = sbi[j + 128], bhN = sbh[j + 128];
        float fw = yout ? fcw[j] : 0.f;
        float2 vR = unp2(aR), vZ = unp2(aZ), vNi = unp2(aNi), vNh = unp2(aNh);
        float part[2] = {0.f, 0.f};
        #pragma unroll
        for (int u = 0; u < 2; u++) {
            int rr = roff + u;
            long r = r0 + rr;
            float avR = u ? vR.y : vR.x;
            float avZ = u ? vZ.y : vZ.x;
            float avNi = u ? vNi.y : vNi.x;
            float avNh = u ? vNh.y : vNh.x;
            float hold = sxh[(DGRU+j)*XS + rr];
            float rg = sigm(avR + bR);
            float z  = sigm(avZ + bZ);
            float nn = tanhf(avNi + biN + rg*(avNh + bhN));
            float hf = (1.f - z)*nn + z*hold;   // cols 0..15: always update
            h[r*HH + j] = hf;
            part[u] += hf * fw;
        }
        if (yout) {
            // held columns 16..63 contribute their staged value
            #pragma unroll
            for (int k = 0; k < 3; k++) {
                int j2 = 16 + jh + k*16;
                float fw2 = fcw[j2];
                #pragma unroll
                for (int u = 0; u < 2; u++)
                    part[u] += sxh[(DGRU+j2)*XS + roff + u] * fw2;
            }
            #pragma unroll
            for (int u = 0; u < 2; u++) {
                float v = part[u];
                v += __shfl_xor_sync(0xffffffffu, v, 8);
                v += __shfl_xor_sync(0xffffffffu, v, 4);
                v += __shfl_xor_sync(0xffffffffu, v, 2);
                v += __shfl_xor_sync(0xffffffffu, v, 1);
                if (jh == 0) {
                    long r = r0 + roff + u;
                    float y = v + fcb[0];
                    ycomp[r] = y;
                    if (ynext) ynext[r*DIN] = y;
                    int b = (int)(r / nnodes), n = (int)(r % nnodes);
                    yout[((size_t)b*TP + step)*nnodes + n] = y;
                }
            }
        }
        __syncthreads();
    }
}

// ================= MEGAKERNEL =================
struct MegaP {
    const float *features, *c_features, *x_hist, *c_x_hist;
    const float *adj_sta, *adj_city, *afc;
    const float *gwi_s, *gwh_s, *gbi_s, *gbh_s;
    const float *gwi_c, *gwh_c, *gbi_c, *gbh_c;
    const float *conv_w, *conv_b, *c_conv_w, *c_conv_b;
    const float *c2s_w, *c2s_b, *s2c_w, *s2c_b;
    const float *fc_w, *fc_b, *c_fc_w, *c_fc_b;
    float *out_s, *out_c;
};

#define SCRATCH_FLOATS (56*64 + 64 + 64*64 + 56*XS + 64*XS + 64)
#define MEGA_SMEM_FLOATS (DGRU*NG + HH*NG + NG + NG + SCRATCH_FLOATS)

__global__ __launch_bounds__(NTHR, 1) void k_mega(MegaP P) {
    extern __shared__ float sm[];
    float* swi = sm;
    float* swh = swi + DGRU*NG;
    float* sbi = swh + HH*NG;
    float* sbh = sbi + NG;
    float* scratch = sbh + NG;

    int bid = blockIdx.x, tid = threadIdx.x;
    bool isC = bid >= NBLK_S;
    int t0 = isC ? (bid - NBLK_S) : bid;
    int tstep = isC ? NBLK_C : NBLK_S;

    // persistent GRU weights
    {
        const float* wi = isC ? P.gwi_c : P.gwi_s;
        const float* wh = isC ? P.gwh_c : P.gwh_s;
        const float* bi = isC ? P.gbi_c : P.gbi_s;
        const float* bh = isC ? P.gbh_c : P.gbh_s;
        for (int i = tid; i < DGRU*NG; i += NTHR) swi[i] = wi[i];
        for (int i = tid; i < HH*NG; i += NTHR) swh[i] = wh[i];
        if (tid < NG) { sbi[tid] = bi[tid]; sbh[tid] = bh[tid]; }
    }

    hist_stage_phase(P.x_hist, P.features, P.c_x_hist, P.c_features);
    buildpx_phase(P.features, P.c_features);
    counts_phase(P.adj_sta, P.afc, P.adj_city);
    gbar();
    scan_phase(scratch);
    gbar();
    fills_phase(P.adj_sta, P.afc, P.adj_city);
    gbar();
    prep2_phase(P.x_hist, P.c_x_hist);
    gbar();
    // history cheb + z
    if (!isC)
        chebz_phase(scratch, g_xs, g_Lxs, P.conv_w, P.conv_b, P.s2c_w,
                    g_xgs, g_zsh, t0, tstep, (THIST*RS) >> 7, 0, nullptr);
    else
        chebz_phase(scratch, g_xc, g_Lxc, P.c_conv_w, P.c_conv_b, P.c2s_w,
                    g_xgc, g_zch, t0, tstep, (THIST*RC) >> 7, 0, nullptr);
    gbar();
    // history GRU (7 steps, scatter fused)
    #pragma unroll 1
    for (int t = 0; t < THIST; t++) {
        int idx = 1 + t;
        bool full = ((idx & 3) == 0);
        bool odd  = ((idx & 1) != 0);
        if (!isC) {
            if (full)
                gru_phase<2>(swi, swh, sbi, sbh, scratch,
                      g_xs + (size_t)t*RS*DIN, g_xgs + (size_t)t*RS*GF,
                      g_zch + (size_t)t*RC*GF, P.c2s_b,
                      g_afc_rowptr, g_afc_cols, NCIT*16, 12,
                      g_hs, t0, tstep, RS >> 7, idx,
                      nullptr, nullptr, nullptr, nullptr, nullptr, NSTA, 0);
            else if (odd)
                gruh_phase(swi, swh, sbi, sbh, scratch,
                      g_xs + (size_t)t*RS*DIN, g_xgs + (size_t)t*RS*GF,
                      g_zch + (size_t)t*RC*GF, P.c2s_b,
                      g_afc_rowptr, g_afc_cols, NCIT*16, 12,
                      g_hs, t0, tstep, RS >> 7,
                      nullptr, nullptr, nullptr, nullptr, nullptr, NSTA, 0);
            else
                gru_phase<1>(swi, swh, sbi, sbh, scratch,
                      g_xs + (size_t)t*RS*DIN, g_xgs + (size_t)t*RS*GF,
                      g_zch + (size_t)t*RC*GF, P.c2s_b,
                      g_afc_rowptr, g_afc_cols, NCIT*16, 12,
                      g_hs, t0, tstep, RS >> 7, idx,
                      nullptr, nullptr, nullptr, nullptr, nullptr, NSTA, 0);
        } else {
            if (full)
                gru_phase<2>(swi, swh, sbi, sbh, scratch,
                      g_xc + (size_t)t*RC*DIN, g_xgc + (size_t)t*RC*GF,
                      g_zsh + (size_t)t*RS*GF, P.s2c_b,
                      g_afcT_rowptr, g_afcT_cols, NSTA*16, 8,
                      g_hc, t0, tstep, RC >> 7, idx,
                      nullptr, nullptr, nullptr, nullptr, nullptr, NCIT, 0);
            else if (odd)
                gruh_phase(swi, swh, sbi, sbh, scratch,
                      g_xc + (size_t)t*RC*DIN, g_xgc + (size_t)t*RC*GF,
                      g_zsh + (size_t)t*RS*GF, P.s2c_b,
                      g_afcT_rowptr, g_afcT_cols, NSTA*16, 8,
                      g_hc, t0, tstep, RC >> 7,
                      nullptr, nullptr, nullptr, nullptr, nullptr, NCIT, 0);
            else
                gru_phase<1>(swi, swh, sbi, sbh, scratch,
                      g_xc + (size_t)t*RC*DIN, g_xgc + (size_t)t*RC*GF,
                      g_zsh + (size_t)t*RS*GF, P.s2c_b,
                      g_afcT_rowptr, g_afcT_cols, NSTA*16, 8,
                      g_hc, t0, tstep, RC >> 7, idx,
                      nullptr, nullptr, nullptr, nullptr, nullptr, NCIT, 0);
        }
        gbar();
    }
    // pred loop (24 steps, 2 phases each)
    #pragma unroll 1
    for (int s = 0; s < TP; s++) {
        int idx = TH + s;
        bool full = ((idx & 3) == 0);
        bool odd  = ((idx & 1) != 0);
        float* pxs_s  = g_pxs  + (size_t)s*SPS;
        float* pLxs_s = g_pLxs + (size_t)s*SPS;
        float* pxc_s  = g_pxc  + (size_t)s*SPC;
        float* pLxc_s = g_pLxc + (size_t)s*SPC;
        if (!isC)
            chebz_phase(scratch, pxs_s, pLxs_s, P.conv_w, P.conv_b, P.s2c_w,
                        g_xgs, g_zsh, t0, tstep, RS >> 7, 1, g_ys);
        else
            chebz_phase(scratch, pxc_s, pLxc_s, P.c_conv_w, P.c_conv_b, P.c2s_w,
                        g_xgc, g_zch, t0, tstep, RC >> 7, 2, g_yc);
        gbar();
        float* ynext_s = (s + 1 < TP) ? (g_pxs + (size_t)(s+1)*SPS) : nullptr;
        float* ynext_c = (s + 1 < TP) ? (g_pxc + (size_t)(s+1)*SPC) : nullptr;
        if (!isC) {
            if (full)
                gru_phase<2>(swi, swh, sbi, sbh, scratch,
                      pxs_s, g_xgs, g_zch, P.c2s_b,
                      g_afc_rowptr, g_afc_cols, NCIT*16, 12,
                      g_hs, t0, tstep, RS >> 7, idx,
                      P.fc_w, P.fc_b, g_ys, ynext_s, P.out_s, NSTA, s);
            else if (odd)
                gruh_phase(swi, swh, sbi, sbh, scratch,
                      pxs_s, g_xgs, g_zch, P.c2s_b,
                      g_afc_rowptr, g_afc_cols, NCIT*16, 12,
                      g_hs, t0, tstep, RS >> 7,
                      P.fc_w, P.fc_b, g_ys, ynext_s, P.out_s, NSTA, s);
            else
                gru_phase<1>(swi, swh, sbi, sbh, scratch,
                      pxs_s, g_xgs, g_zch, P.c2s_b,
                      g_afc_rowptr, g_afc_cols, NCIT*16, 12,
                      g_hs, t0, tstep, RS >> 7, idx,
                      P.fc_w, P.fc_b, g_ys, ynext_s, P.out_s, NSTA, s);
        } else {
            if (full)
                gru_phase<2>(swi, swh, sbi, sbh, scratch,
                      pxc_s, g_xgc, g_zsh, P.s2c_b,
                      g_afcT_rowptr, g_afcT_cols, NSTA*16, 8,
                      g_hc, t0, tstep, RC >> 7, idx,
                      P.c_fc_w, P.c_fc_b, g_yc, ynext_c, P.out_c, NCIT, s);
            else if (odd)
                gruh_phase(swi, swh, sbi, sbh, scratch,
                      pxc_s, g_xgc, g_zsh, P.s2c_b,
                      g_afcT_rowptr, g_afcT_cols, NSTA*16, 8,
                      g_hc, t0, tstep, RC >> 7,
                      P.c_fc_w, P.c_fc_b, g_yc, ynext_c, P.out_c, NCIT, s);
            else
                gru_phase<1>(swi, swh, sbi, sbh, scratch,
                      pxc_s, g_xgc, g_zsh, P.s2c_b,
                      g_afcT_rowptr, g_afcT_cols, NSTA*16, 8,
                      g_hc, t0, tstep, RC >> 7, idx,
                      P.c_fc_w, P.c_fc_b, g_yc, ynext_c, P.out_c, NCIT, s);
        }
        gbar();
    }
}

// ---------------- host ----------------
extern "C" void kernel_launch(void* const* d_in, const int* in_sizes, int n_in,
                              void* d_out, int out_size) {
    MegaP P;
    P.x_hist     = (const float*)d_in[0];
    P.features   = (const float*)d_in[1];
    P.c_x_hist   = (const float*)d_in[2];
    P.c_features = (const float*)d_in[3];
    P.adj_sta    = (const float*)d_in[4];
    P.adj_city   = (const float*)d_in[5];
    P.afc        = (const float*)d_in[6];
    P.conv_w     = (const float*)d_in[7];
    P.conv_b     = (const float*)d_in[8];
    P.c_conv_w   = (const float*)d_in[9];
    P.c_conv_b   = (const float*)d_in[10];
    P.gwi_s      = (const float*)d_in[11];
    P.gwh_s      = (const float*)d_in[12];
    P.gbi_s      = (const float*)d_in[13];
    P.gbh_s      = (const float*)d_in[14];
    P.gwi_c      = (const float*)d_in[15];
    P.gwh_c      = (const float*)d_in[16];
    P.gbi_c      = (const float*)d_in[17];
    P.gbh_c      = (const float*)d_in[18];
    P.fc_w       = (const float*)d_in[19];
    P.fc_b       = (const float*)d_in[20];
    P.c_fc_w     = (const float*)d_in[21];
    P.c_fc_b     = (const float*)d_in[22];
    P.c2s_w      = (const float*)d_in[23];
    P.c2s_b      = (const float*)d_in[24];
    P.s2c_w      = (const float*)d_in[25];
    P.s2c_b      = (const float*)d_in[26];
    P.out_s = (float*)d_out;
    P.out_c = P.out_s + (size_t)NB * TP * NSTA;

    (void)in_sizes; (void)n_in; (void)out_size;

    const int mega_smem = MEGA_SMEM_FLOATS * (int)sizeof(float);
    cudaFuncSetAttribute(k_mega, cudaFuncAttributeMaxDynamicSharedMemorySize, mega_smem);
    k_mega<<<NBLK, NTHR, mega_smem>>>(P);
}

// round 17
// speedup vs baseline: 1.1211x; 1.0586x over previous
#include <cuda_runtime.h>
#include <math.h>

#define NSTA 4096
#define NCIT 256
#define NB 8
#define TH 8
#define TP 24
#define TT 32
#define DIN 28
#define DM 27
#define GF 64
#define HH 64
#define NG 192
#define DGRU 92
#define THIST 7
#define NNZMAX (1<<20)

#define NBLK   148
#define NBLK_S 128
#define NBLK_C 20
#define NTHR   1024
#define XS     130     // smem tile row-stride

#define SPS (NB*NSTA*DIN)
#define SPC (NB*NCIT*DIN)
#define RS  (NB*NSTA)
#define RC  (NB*NCIT)

typedef unsigned long long ull;

// ---------------- static device scratch ----------------
__device__ float g_dinv_s[NSTA];
__device__ int   g_cnt_s[NSTA];
__device__ int   g_Ls_rowptr[NSTA+1];
__device__ int   g_Ls_cols[NNZMAX];
__device__ float g_Ls_vals[NNZMAX];

__device__ int   g_cnt_afc[NSTA];
__device__ int   g_afc_rowptr[NSTA+1];
__device__ int   g_afc_cols[NNZMAX];

__device__ int   g_cnt_afcT[NCIT];
__device__ int   g_afcT_rowptr[NCIT+1];
__device__ int   g_afcT_cols[NNZMAX];

__device__ float g_dinv_c[NCIT];
__device__ int   g_cnt_c[NCIT];
__device__ float g_Lc[NCIT*NCIT];

// history buffers
__device__ float g_xs [THIST*RS*DIN];
__device__ float g_Lxs[THIST*RS*DIN];
__device__ float g_xgs[THIST*RS*GF];

__device__ float g_xc [THIST*RC*DIN];
__device__ float g_Lxc[THIST*RC*DIN];
__device__ float g_xgc[THIST*RC*GF];
__device__ float g_zch[THIST*RC*GF];

// pred precomputed x / Lx (all 24 steps)
__device__ float g_pxs [TP*SPS];
__device__ float g_pLxs[TP*SPS];
__device__ float g_pxc [TP*SPC];
__device__ float g_pLxc[TP*SPC];

__device__ float g_hs[RS*HH];
__device__ float g_hc[RC*HH];
__device__ float g_ys[RS];
__device__ float g_yc[RC];

// grid barrier state
__device__ unsigned g_bar_cnt = 0;
__device__ volatile unsigned g_bar_gen = 0;

// ---------------- helpers ----------------
__device__ __forceinline__ ull splat2(float w) {
    ull r;
    asm("mov.b64 %0, {%1, %1};" : "=l"(r) : "f"(w));
    return r;
}
__device__ __forceinline__ void fma2(ull& a, ull x, ull w) {
    asm("fma.rn.f32x2 %0, %1, %2, %0;" : "+l"(a) : "l"(x), "l"(w));
}
__device__ __forceinline__ float2 unp2(ull v) {
    float2 f;
    asm("mov.b64 {%0, %1}, %2;" : "=f"(f.x), "=f"(f.y) : "l"(v));
    return f;
}
__device__ __forceinline__ float sigm(float x) { return 1.f / (1.f + __expf(-x)); }

__device__ __forceinline__ void gbar() {
    __syncthreads();
    if (threadIdx.x == 0) {
        unsigned gen = g_bar_gen;
        __threadfence();
        unsigned t = atomicAdd(&g_bar_cnt, 1);
        if (t == (unsigned)(NBLK - 1)) {
            g_bar_cnt = 0;
            __threadfence();
            g_bar_gen = gen + 1;
        } else {
            while (g_bar_gen == gen) { __nanosleep(64); }
        }
    }
    __syncthreads();
    __threadfence();
}

__device__ __forceinline__ int wredi(int c) {
    #pragma unroll
    for (int o = 16; o; o >>= 1) c += __shfl_xor_sync(0xffffffffu, c, o);
    return c;
}

// ---------------- preproc device functions ----------------
__device__ __noinline__ void counts_phase(const float* adj_sta, const float* afc,
                                          const float* adj_city) {
    int gw = (blockIdx.x*NTHR + threadIdx.x) >> 5;
    int lane = threadIdx.x & 31;
    const int NW = NBLK*(NTHR/32);
    for (int m = gw; m < NSTA; m += NW) {
        int c = 0;
        const float* row = adj_sta + (size_t)m*NSTA;
        for (int j = lane; j < NSTA; j += 32) c += (row[j] != 0.f && j != m);
        c = wredi(c);
        if (lane == 0) { g_cnt_s[m] = c; g_dinv_s[m] = c > 0 ? rsqrtf((float)c) : 0.f; }
    }
    for (int m = gw; m < NSTA; m += NW) {
        int c = 0;
        const float* row = afc + (size_t)m*NCIT;
        for (int j = lane; j < NCIT; j += 32) c += (row[j] != 0.f);
        c = wredi(c);
        if (lane == 0) g_cnt_afc[m] = c;
    }
    for (int cc = gw; cc < NCIT; cc += NW) {
        int c = 0;
        for (int s = lane; s < NSTA; s += 32) c += (afc[(size_t)s*NCIT + cc] != 0.f);
        c = wredi(c);
        if (lane == 0) g_cnt_afcT[cc] = c;
    }
    for (int m = gw; m < NCIT; m += NW) {
        int c = 0;
        const float* row = adj_city + (size_t)m*NCIT;
        for (int j = lane; j < NCIT; j += 32) c += (row[j] != 0.f && j != m);
        c = wredi(c);
        if (lane == 0) { g_cnt_c[m] = c; g_dinv_c[m] = c > 0 ? rsqrtf((float)c) : 0.f; }
    }
}

__device__ __noinline__ void scan_phase(float* scratch) {
    if (blockIdx.x >= 3) return;
    int* s = (int*)scratch;
    const int* cnt; int* rp; int n;
    if (blockIdx.x == 0) { cnt = g_cnt_s; rp = g_Ls_rowptr; n = NSTA; }
    else if (blockIdx.x == 1) { cnt = g_cnt_afc; rp = g_afc_rowptr; n = NSTA; }
    else { cnt = g_cnt_afcT; rp = g_afcT_rowptr; n = NCIT; }
    int tid = threadIdx.x;
    int per = (n + NTHR - 1) / NTHR;
    int base = tid * per;
    int loc = 0;
    for (int i = 0; i < per; i++) if (base + i < n) loc += cnt[base + i];
    s[tid] = loc; __syncthreads();
    for (int off = 1; off < NTHR; off <<= 1) {
        int v = (tid >= off) ? s[tid - off] : 0;
        __syncthreads();
        s[tid] += v;
        __syncthreads();
    }
    int a = tid ? s[tid - 1] : 0;
    for (int i = 0; i < per; i++)
        if (base + i < n) { rp[base + i] = a; a += cnt[base + i]; }
    if (tid == NTHR - 1) rp[n] = a;
}

__device__ void fill_csr_row(const float* __restrict__ mat, const int* __restrict__ rowptr,
                             int* __restrict__ cols, float* __restrict__ vals,
                             const float* __restrict__ dinv,
                             int ncols, int excl, int m) {
    int lane = threadIdx.x & 31;
    int pos = rowptr[m];
    float dm = dinv ? dinv[m] : 0.f;
    for (int base = 0; base < ncols; base += 32) {
        int j = base + lane;
        bool p = (j < ncols) && (mat[(size_t)m*ncols + j] != 0.f) && !(excl && j == m);
        unsigned msk = __ballot_sync(0xffffffffu, p);
        if (p) {
            int off = __popc(msk & ((1u << lane) - 1u));
            cols[pos + off] = j;
            if (vals) vals[pos + off] = -dm * dinv[j];
        }
        pos += __popc(msk);
    }
}

__device__ void fill_csrT_col(const float* __restrict__ mat, const int* __restrict__ rowptr,
                              int* __restrict__ cols, int nrows, int ncols, int c) {
    int lane = threadIdx.x & 31;
    int pos = rowptr[c];
    for (int base = 0; base < nrows; base += 32) {
        int s = base + lane;
        bool p = (s < nrows) && (mat[(size_t)s*ncols + c] != 0.f);
        unsigned msk = __ballot_sync(0xffffffffu, p);
        if (p) cols[pos + __popc(msk & ((1u << lane) - 1u))] = s;
        pos += __popc(msk);
    }
}

__device__ __noinline__ void fills_phase(const float* adj_sta, const float* afc,
                                         const float* adj_city) {
    int gw = (blockIdx.x*NTHR + threadIdx.x) >> 5;
    const int NW = NBLK*(NTHR/32);
    for (int m = gw; m < NSTA; m += NW)
        fill_csr_row(adj_sta, g_Ls_rowptr, g_Ls_cols, g_Ls_vals, g_dinv_s, NSTA, 1, m);
    for (int m = gw; m < NSTA; m += NW)
        fill_csr_row(afc, g_afc_rowptr, g_afc_cols, nullptr, nullptr, NCIT, 0, m);
    for (int c = gw; c < NCIT; c += NW)
        fill_csrT_col(afc, g_afcT_rowptr, g_afcT_cols, NSTA, NCIT, c);
    int g = blockIdx.x*NTHR + threadIdx.x;
    for (int i = g; i < NCIT*NCIT; i += NBLK*NTHR) {
        int m = i >> 8, n = i & 255;
        float v = 0.f;
        if (n != m && adj_city[i] != 0.f) v = -g_dinv_c[m]*g_dinv_c[n];
        g_Lc[i] = v;
    }
}

__device__ __noinline__ void hist_stage_phase(const float* xh_s, const float* ft_s,
                                              const float* xh_c, const float* ft_c) {
    int g = blockIdx.x*NTHR + threadIdx.x;
    const int GS = NBLK*NTHR;
    const int nS = THIST*RS*DIN;
    for (int i = g; i < nS; i += GS) {
        int ch = i % DIN; int r = i / DIN; int n = r % NSTA; int tb = r / NSTA;
        int b = tb % NB; int t = tb / NB;
        g_xs[i] = (ch == 0) ? xh_s[(b*TH + t)*NSTA + n]
                            : ft_s[((size_t)(b*TT + (t+1))*NSTA + n)*DM + (ch-1)];
    }
    const int nC = THIST*RC*DIN;
    for (int i = g; i < nC; i += GS) {
        int ch = i % DIN; int r = i / DIN; int n = r % NCIT; int tb = r / NCIT;
        int b = tb % NB; int t = tb / NB;
        g_xc[i] = (ch == 0) ? xh_c[(b*TH + t)*NCIT + n]
                            : ft_c[((size_t)(b*TT + (t+1))*NCIT + n)*DM + (ch-1)];
    }
}

__device__ __noinline__ void buildpx_phase(const float* ft_s, const float* ft_c) {
    int g = blockIdx.x*NTHR + threadIdx.x;
    const int GS = NBLK*NTHR;
    const int totS = TP*NB*NSTA*DM;
    for (int i = g; i < totS; i += GS) {
        int ch = i % DM; int q = i / DM;
        int n = q & (NSTA-1); q >>= 12;
        int b = q & 7; int s = q >> 3;
        g_pxs[((size_t)(s*NB+b)*NSTA + n)*DIN + 1 + ch] =
            ft_s[(((size_t)b*TT + TH + s)*NSTA + n)*DM + ch];
    }
    const int totC = TP*NB*NCIT*DM;
    for (int i = g; i < totC; i += GS) {
        int ch = i % DM; int q = i / DM;
        int n = q & (NCIT-1); q >>= 8;
        int b = q & 7; int s = q >> 3;
        g_pxc[((size_t)(s*NB+b)*NCIT + n)*DIN + 1 + ch] =
            ft_c[(((size_t)b*TT + TH + s)*NCIT + n)*DM + ch];
    }
}

// histL + pred feature pLx + h/y init
__device__ __noinline__ void prep2_phase(const float* x_hist, const float* c_x_hist) {
    int gw = (blockIdx.x*NTHR + threadIdx.x) >> 5;
    int lane = threadIdx.x & 31;
    const int NW = NBLK*(NTHR/32);
    const int tasks = NSTA*THIST*NB;
    for (int t = gw; t < tasks; t += NW) {
        int m = t / (THIST*NB);
        int tb = t % (THIST*NB);
        int beg = g_Ls_rowptr[m], end = g_Ls_rowptr[m+1];
        const float* xb = g_xs + (size_t)tb*NSTA*DIN;
        if (lane < DIN) {
            float acc = 0.f;
            for (int p = beg; p < end; p++)
                acc += g_Ls_vals[p] * xb[g_Ls_cols[p]*DIN + lane];
            g_Lxs[((size_t)tb*NSTA + m)*DIN + lane] = acc;
        }
    }
    const int ptasks = TP*RS;
    for (int t = gw; t < ptasks; t += NW) {
        int n = t & (NSTA-1); int q = t >> 12;
        int b = q & 7; int s = q >> 3;
        int beg = g_Ls_rowptr[n], end = g_Ls_rowptr[n+1];
        const float* xb = g_pxs + (size_t)(s*NB+b)*NSTA*DIN;
        if (lane < DM) {
            float acc = 0.f;
            for (int p = beg; p < end; p++)
                acc += g_Ls_vals[p] * xb[g_Ls_cols[p]*DIN + 1 + lane];
            g_pLxs[((size_t)(s*NB+b)*NSTA + n)*DIN + 1 + lane] = acc;
        }
    }
    int g = blockIdx.x*NTHR + threadIdx.x;
    const int GS = NBLK*NTHR;
    for (int i = g; i < THIST*RC*DIN; i += GS) {
        int ch = i % DIN; int r = i / DIN; int m = r % NCIT; int tb = r / NCIT;
        const float* xb = g_xc + (size_t)tb*NCIT*DIN;
        float acc = 0.f;
        for (int j = 0; j < NCIT; j++) acc += g_Lc[m*NCIT + j]*xb[j*DIN + ch];
        g_Lxc[i] = acc;
    }
    for (int i = g; i < TP*RC*DM; i += GS) {
        int ch = i % DM; int q = i / DM;
        int n = q & (NCIT-1); q >>= 8;
        int b = q & 7; int s = q >> 3;
        const float* xb = g_pxc + (size_t)(s*NB+b)*NCIT*DIN;
        float acc = 0.f;
        for (int j = 0; j < NCIT; j++) acc += g_Lc[n*NCIT + j]*xb[j*DIN + 1 + ch];
        g_pLxc[((size_t)(s*NB+b)*NCIT + n)*DIN + 1 + ch] = acc;
    }
    for (int i = g; i < RS*HH; i += GS) g_hs[i] = 0.f;
    for (int i = g; i < RC*HH; i += GS) g_hc[i] = 0.f;
    for (int i = g; i < RS; i += GS) {
        int b = i >> 12, n = i & (NSTA-1);
        float y = x_hist[(b*TH + TH-1)*NSTA + n];
        g_ys[i] = y; g_pxs[(size_t)i*DIN] = y;
    }
    for (int i = g; i < RC; i += GS) {
        int b = i >> 8, n = i & (NCIT-1);
        float y = c_x_hist[(b*TH + TH-1)*NCIT + n];
        g_yc[i] = y; g_pxc[(size_t)i*DIN] = y;
    }
}

// ---------------- cheb (+optional zgemm) phase ----------------
__device__ __noinline__ void chebz_phase(float* scratch,
        const float* x, const float* lx,
        const float* wc, const float* bc, const float* wz,
        float* xg_out, float* z_out,
        int t0, int tstep, int nt,
        int ymode, const float* yvec, int compute_z) {
    float* swc = scratch;            // 56*64
    float* sb  = swc + 56*64;        // 64
    float* swz = sb + 64;            // 64*64
    float* sxt = swz + 64*64;        // 56*XS
    float* stp = sxt + 56*XS;        // 64*XS
    int tid = threadIdx.x, tx = tid & 31, wid = tid >> 5;
    for (int i = tid; i < 56*64; i += NTHR) swc[i] = wc[i];
    if (compute_z)
        for (int i = tid; i < 64*64; i += NTHR) swz[i] = wz[i];
    if (tid < 64) sb[tid] = bc[tid];
    __syncthreads();
    const int xoff = wid * 4;
    for (int tile = t0; tile < nt; tile += tstep) {
        long r0 = (long)tile << 7;
        for (int i = tid; i < 14*128; i += NTHR) {
            int rr = i & 127, c4 = i >> 7;
            long r = r0 + rr;
            float4 v; int chb;
            if (c4 < 7) { v = *(const float4*)(x + r*DIN + c4*4); chb = c4*4; }
            else { v = *(const float4*)(lx + r*DIN + (c4-7)*4); chb = DIN + (c4-7)*4; }
            sxt[(chb+0)*XS+rr] = v.x; sxt[(chb+1)*XS+rr] = v.y;
            sxt[(chb+2)*XS+rr] = v.z; sxt[(chb+3)*XS+rr] = v.w;
        }
        if (ymode) {
            __syncthreads();
            if (ymode == 1) {
                for (int rr = wid; rr < 128; rr += 32) {
                    long r = r0 + rr;
                    int b = (int)(r >> 12), node = (int)(r & (NSTA-1));
                    const float* yb = yvec + b*NSTA;
                    int beg = g_Ls_rowptr[node], end = g_Ls_rowptr[node+1];
                    float acc = 0.f;
                    for (int p = beg + tx; p < end; p += 32)
                        acc += g_Ls_vals[p] * yb[g_Ls_cols[p]];
                    #pragma unroll
                    for (int o = 16; o; o >>= 1) acc += __shfl_xor_sync(0xffffffffu, acc, o);
                    if (tx == 0) sxt[DIN*XS + rr] = acc;
                }
            } else {
                for (int rr = wid; rr < 128; rr += 32) {
                    long r = r0 + rr;
                    int b = (int)(r >> 8), node = (int)(r & (NCIT-1));
                    const float* yb = yvec + b*NCIT;
                    const float* Lrow = g_Lc + node*NCIT;
                    float acc = 0.f;
                    for (int j = tx; j < NCIT; j += 32) acc += Lrow[j]*yb[j];
                    #pragma unroll
                    for (int o = 16; o; o >>= 1) acc += __shfl_xor_sync(0xffffffffu, acc, o);
                    if (tx == 0) sxt[DIN*XS + rr] = acc;
                }
            }
        }
        __syncthreads();
        // GEMM1: xg = sigm([x|Lx]@Wc + b)
        {
            ull a0[2] = {0,0}, a1[2] = {0,0};
            #pragma unroll 4
            for (int ch = 0; ch < 56; ch++) {
                const float* xr = &sxt[ch*XS + xoff];
                ull xv0 = *(const ull*)(xr);
                ull xv1 = *(const ull*)(xr + 2);
                float2 wv = *(const float2*)&swc[ch*64 + 2*tx];
                ull w0 = splat2(wv.x), w1 = splat2(wv.y);
                fma2(a0[0], xv0, w0); fma2(a0[1], xv1, w0);
                fma2(a1[0], xv0, w1); fma2(a1[1], xv1, w1);
            }
            float b0 = sb[2*tx], b1 = sb[2*tx+1];
            #pragma unroll
            for (int rk = 0; rk < 2; rk++) {
                float2 v0 = unp2(a0[rk]), v1 = unp2(a1[rk]);
                int rr = xoff + rk*2;
                long r = r0 + rr;
                float g00 = sigm(v0.x + b0), g01 = sigm(v1.x + b1);
                float g10 = sigm(v0.y + b0), g11 = sigm(v1.y + b1);
                *(float2*)&xg_out[r*64 + 2*tx]     = make_float2(g00, g01);
                *(float2*)&xg_out[(r+1)*64 + 2*tx] = make_float2(g10, g11);
                if (compute_z) {
                    stp[(2*tx)*XS + rr]     = g00;
                    stp[(2*tx+1)*XS + rr]   = g01;
                    stp[(2*tx)*XS + rr+1]   = g10;
                    stp[(2*tx+1)*XS + rr+1] = g11;
                }
            }
        }
        __syncthreads();
        // GEMM2: z = xg @ Wz
        if (compute_z) {
            ull c0[2] = {0,0}, c1[2] = {0,0};
            #pragma unroll 4
            for (int ch = 0; ch < 64; ch++) {
                const float* xr = &stp[ch*XS + xoff];
                ull xv0 = *(const ull*)(xr);
                ull xv1 = *(const ull*)(xr + 2);
                float2 wv = *(const float2*)&swz[ch*64 + 2*tx];
                ull w0 = splat2(wv.x), w1 = splat2(wv.y);
                fma2(c0[0], xv0, w0); fma2(c0[1], xv1, w0);
                fma2(c1[0], xv0, w1); fma2(c1[1], xv1, w1);
            }
            #pragma unroll
            for (int rk = 0; rk < 2; rk++) {
                float2 v0 = unp2(c0[rk]), v1 = unp2(c1[rk]);
                long r = r0 + xoff + rk*2;
                *(float2*)&z_out[r*64 + 2*tx]     = make_float2(v0.x, v1.x);
                *(float2*)&z_out[(r+1)*64 + 2*tx] = make_float2(v0.y, v1.y);
            }
            __syncthreads();
        }
    }
}

// ---------------- shared staging for GRU ----------------
// CITY=false: gather z_city (precomputed) + xg + bias   (station path, unchanged)
// CITY=true : gather xg_station, then per-warp GEMM with cityW + bias + xgc (reassociated)
template<bool CITY>
__device__ __forceinline__ void gru_stage(float* sxh,
        const float* xa, const float* xg, const float* zo, const float* fb,
        const int* rp, const int* cols, int zo_stride16, int nshift,
        const float* h, long r0, const float* cityW) {
    int tid = threadIdx.x, tx = tid & 31, wid = tid >> 5;
    if (!CITY) {
        for (int i = tid; i < 128*16; i += NTHR) {
            int rr = i >> 4, c4 = i & 15;
            long r = r0 + rr;
            int tb = (int)(r >> nshift), node = (int)(r & ((1 << nshift) - 1));
            float4 acc = ((const float4*)fb)[c4];
            int beg = rp[node], end = rp[node+1];
            const float4* src = (const float4*)zo + (size_t)tb * zo_stride16;
            for (int p = beg; p < end; p++) {
                float4 v = src[cols[p]*16 + c4];
                acc.x += v.x; acc.y += v.y; acc.z += v.z; acc.w += v.w;
            }
            float4 xv = ((const float4*)xg)[r*16 + c4];
            acc.x += xv.x; acc.y += xv.y; acc.z += xv.z; acc.w += xv.w;
            int chb = DIN + c4*4;
            sxh[(chb+0)*XS+rr] = acc.x; sxh[(chb+1)*XS+rr] = acc.y;
            sxh[(chb+2)*XS+rr] = acc.z; sxh[(chb+3)*XS+rr] = acc.w;
        }
    } else {
        // gather tmp = afcT @ xg_station into the fx channel region
        for (int i = tid; i < 128*16; i += NTHR) {
            int rr = i >> 4, c4 = i & 15;
            long r = r0 + rr;
            int tb = (int)(r >> nshift), node = (int)(r & ((1 << nshift) - 1));
            float4 acc = make_float4(0.f, 0.f, 0.f, 0.f);
            int beg = rp[node], end = rp[node+1];
            const float4* src = (const float4*)zo + (size_t)tb * zo_stride16;
            for (int p = beg; p < end; p++) {
                float4 v = src[cols[p]*16 + c4];
                acc.x += v.x; acc.y += v.y; acc.z += v.z; acc.w += v.w;
            }
            int chb = DIN + c4*4;
            sxh[(chb+0)*XS+rr] = acc.x; sxh[(chb+1)*XS+rr] = acc.y;
            sxh[(chb+2)*XS+rr] = acc.z; sxh[(chb+3)*XS+rr] = acc.w;
        }
        __syncthreads();
        // per-warp GEMM: fx = xgc + fb + tmp @ cityW (in place; per-warp row ownership)
        const int xoff = wid * 4;
        ull a0[2] = {0,0}, a1[2] = {0,0};
        #pragma unroll 4
        for (int ch = 0; ch < 64; ch++) {
            const float* xr = &sxh[(DIN+ch)*XS + xoff];
            ull xv0 = *(const ull*)(xr);
            ull xv1 = *(const ull*)(xr + 2);
            float2 wv = *(const float2*)&cityW[ch*64 + 2*tx];
            ull w0 = splat2(wv.x), w1 = splat2(wv.y);
            fma2(a0[0], xv0, w0); fma2(a0[1], xv1, w0);
            fma2(a1[0], xv0, w1); fma2(a1[1], xv1, w1);
        }
        float b0 = fb[2*tx], b1 = fb[2*tx+1];
        #pragma unroll
        for (int rk = 0; rk < 2; rk++) {
            float2 v0 = unp2(a0[rk]), v1 = unp2(a1[rk]);
            int rr = xoff + rk*2;
            long r = r0 + rr;
            float2 xg0 = *(const float2*)&xg[r*64 + 2*tx];
            float2 xg1 = *(const float2*)&xg[(r+1)*64 + 2*tx];
            sxh[(DIN+2*tx)*XS + rr]     = xg0.x + b0 + v0.x;
            sxh[(DIN+2*tx+1)*XS + rr]   = xg0.y + b1 + v1.x;
            sxh[(DIN+2*tx)*XS + rr+1]   = xg1.x + b0 + v0.y;
            sxh[(DIN+2*tx+1)*XS + rr+1] = xg1.y + b1 + v1.y;
        }
    }
    // xa + h staging (rr-major: conflict-free)
    for (int i = tid; i < 23*128; i += NTHR) {
        int rr = i & 127, c4 = i >> 7;
        long r = r0 + rr;
        float4 v; int chb;
        if (c4 < 7) { v = *(const float4*)(xa + r*DIN + c4*4); chb = c4*4; }
        else { v = *(const float4*)(h + r*HH + (c4-7)*4); chb = DGRU + (c4-7)*4; }
        sxh[(chb+0)*XS+rr] = v.x; sxh[(chb+1)*XS+rr] = v.y;
        sxh[(chb+2)*XS+rr] = v.z; sxh[(chb+3)*XS+rr] = v.w;
    }
}

// ---------------- GRU phase (templated on active column blocks NC, CITY) ----------
template<int NC, bool CITY>
__device__ __noinline__ void gru_phase(
        const float* swi, const float* swh, const float* sbi, const float* sbh,
        float* sxh,
        const float* xa, const float* xg, const float* zo, const float* fb,
        const int* rp, const int* cols, int zo_stride16, int nshift,
        float* h, int t0, int tstep, int nt, int idx,
        const float* fcw, const float* fcb,
        float* ycomp, float* ynext, float* yout, int nnodes, int step,
        const float* cityW) {
    int tid = threadIdx.x, tx = tid & 31, wid = tid >> 5;
    const int xoff = wid * 4;
    for (int tile = t0; tile < nt; tile += tstep) {
        long r0 = (long)tile << 7;
        gru_stage<CITY>(sxh, xa, xg, zo, fb, rp, cols, zo_stride16, nshift, h, r0, cityW);
        __syncthreads();

        // accumulators: R/Z share (wi+wh summed), N split
        ull aRZ[2*NC][2], aNi[NC][2], aNh[NC][2];
        #pragma unroll
        for (int m = 0; m < 2*NC; m++) { aRZ[m][0] = 0ull; aRZ[m][1] = 0ull; }
        #pragma unroll
        for (int m = 0; m < NC; m++) { aNi[m][0]=aNi[m][1]=0ull; aNh[m][0]=aNh[m][1]=0ull; }

        #pragma unroll 4
        for (int ch = 0; ch < DGRU; ch++) {
            const float* xr = &sxh[ch*XS + xoff];
            ull xv0 = *(const ull*)(xr);
            ull xv1 = *(const ull*)(xr + 2);
            const float* wr = &swi[ch*NG + tx];
            #pragma unroll
            for (int cb = 0; cb < NC; cb++) {
                ull wR = splat2(wr[32*cb]);
                fma2(aRZ[cb][0], xv0, wR); fma2(aRZ[cb][1], xv1, wR);
                ull wZ = splat2(wr[64 + 32*cb]);
                fma2(aRZ[NC+cb][0], xv0, wZ); fma2(aRZ[NC+cb][1], xv1, wZ);
                ull wN = splat2(wr[128 + 32*cb]);
                fma2(aNi[cb][0], xv0, wN); fma2(aNi[cb][1], xv1, wN);
            }
        }
        #pragma unroll 4
        for (int ch = 0; ch < HH; ch++) {
            const float* xr = &sxh[(DGRU+ch)*XS + xoff];
            ull xv0 = *(const ull*)(xr);
            ull xv1 = *(const ull*)(xr + 2);
            const float* wr = &swh[ch*NG + tx];
            #pragma unroll
            for (int cb = 0; cb < NC; cb++) {
                ull wR = splat2(wr[32*cb]);
                fma2(aRZ[cb][0], xv0, wR); fma2(aRZ[cb][1], xv1, wR);
                ull wZ = splat2(wr[64 + 32*cb]);
                fma2(aRZ[NC+cb][0], xv0, wZ); fma2(aRZ[NC+cb][1], xv1, wZ);
                ull wN = splat2(wr[128 + 32*cb]);
                fma2(aNh[cb][0], xv0, wN); fma2(aNh[cb][1], xv1, wN);
            }
        }

        float part[4] = {0.f, 0.f, 0.f, 0.f};
        #pragma unroll
        for (int cb = 0; cb < NC; cb++) {
            int j = cb*32 + tx;
            float bR = sbi[j] + sbh[j];
            float bZ = sbi[j + 64] + sbh[j + 64];
            float biN = sbi[j + 128], bhN = sbh[j + 128];
            int iv = 1 << (j >> 4);
            bool upd = (idx & (iv - 1)) == 0;
            float fw = yout ? fcw[j] : 0.f;
            #pragma unroll
            for (int rk = 0; rk < 2; rk++) {
                float2 vR = unp2(aRZ[cb][rk]);
                float2 vZ = unp2(aRZ[NC+cb][rk]);
                float2 vNi = unp2(aNi[cb][rk]);
                float2 vNh = unp2(aNh[cb][rk]);
                #pragma unroll
                for (int u = 0; u < 2; u++) {
                    int rr = xoff + rk*2 + u;
                    long r = r0 + rr;
                    float avR = u ? vR.y : vR.x;
                    float avZ = u ? vZ.y : vZ.x;
                    float avNi = u ? vNi.y : vNi.x;
                    float avNh = u ? vNh.y : vNh.x;
                    float hold = sxh[(DGRU+j)*XS + rr];
                    float rg = sigm(avR + bR);
                    float z  = sigm(avZ + bZ);
                    float nn = tanhf(avNi + biN + rg*(avNh + bhN));
                    float hf = upd ? ((1.f - z)*nn + z*hold) : hold;
                    if (upd) h[r*HH + j] = hf;
                    part[rk*2 + u] += hf * fw;
                }
            }
        }
        // columns 32..63 untouched when NC==1: contribute their hold value to y
        if (NC == 1 && yout) {
            int j2 = 32 + tx;
            float fw2 = fcw[j2];
            #pragma unroll
            for (int rk = 0; rk < 2; rk++)
                #pragma unroll
                for (int u = 0; u < 2; u++) {
                    int rr = xoff + rk*2 + u;
                    part[rk*2 + u] += sxh[(DGRU+j2)*XS + rr] * fw2;
                }
        }
        if (yout) {
            #pragma unroll
            for (int r4 = 0; r4 < 4; r4++) {
                float v = part[r4];
                v += __shfl_xor_sync(0xffffffffu, v, 16);
                v += __shfl_xor_sync(0xffffffffu, v, 8);
                v += __shfl_xor_sync(0xffffffffu, v, 4);
                v += __shfl_xor_sync(0xffffffffu, v, 2);
                v += __shfl_xor_sync(0xffffffffu, v, 1);
                if (tx == 0) {
                    long r = r0 + xoff + r4;
                    float y = v + fcb[0];
                    ycomp[r] = y;
                    if (ynext) ynext[r*DIN] = y;
                    int b = (int)(r / nnodes), n = (int)(r % nnodes);
                    yout[((size_t)b*TP + step)*nnodes + n] = y;
                }
            }
        }
        __syncthreads();
    }
}

// ---------------- GRU phase HALF: odd idx — only columns 0..15 update -------------
template<bool CITY>
__device__ __noinline__ void gruh_phase(
        const float* swi, const float* swh, const float* sbi, const float* sbh,
        float* sxh,
        const float* xa, const float* xg, const float* zo, const float* fb,
        const int* rp, const int* cols, int zo_stride16, int nshift,
        float* h, int t0, int tstep, int nt,
        const float* fcw, const float* fcb,
        float* ycomp, float* ynext, float* yout, int nnodes, int step,
        const float* cityW) {
    int tid = threadIdx.x, tx = tid & 31, wid = tid >> 5;
    const int xoff = wid * 4;
    int jh = tx & 15;
    int hh2 = tx >> 4;
    const int roff = xoff + hh2*2;
    for (int tile = t0; tile < nt; tile += tstep) {
        long r0 = (long)tile << 7;
        gru_stage<CITY>(sxh, xa, xg, zo, fb, rp, cols, zo_stride16, nshift, h, r0, cityW);
        __syncthreads();

        ull aR = 0ull, aZ = 0ull, aNi = 0ull, aNh = 0ull;
        #pragma unroll 4
        for (int ch = 0; ch < DGRU; ch++) {
            ull xv = *(const ull*)&sxh[ch*XS + roff];
            const float* wr = &swi[ch*NG + jh];
            fma2(aR,  xv, splat2(wr[0]));
            fma2(aZ,  xv, splat2(wr[64]));
            fma2(aNi, xv, splat2(wr[128]));
        }
        #pragma unroll 4
        for (int ch = 0; ch < HH; ch++) {
            ull xv = *(const ull*)&sxh[(DGRU+ch)*XS + roff];
            const float* wr = &swh[ch*NG + jh];
            fma2(aR,  xv, splat2(wr[0]));
            fma2(aZ,  xv, splat2(wr[64]));
            fma2(aNh, xv, splat2(wr[128]));
        }

        int j = jh;
        float bR = sbi[j] + sbh[j];
        float bZ = sbi[j + 64] + sbh[j + 64];
        float biN = sbi[j + 128], bhN = sbh[j + 128];
        float fw = yout ? fcw[j] : 0.f;
        float2 vR = unp2(aR), vZ = unp2(aZ), vNi = unp2(aNi), vNh = unp2(aNh);
        float part[2] = {0.f, 0.f};
        #pragma unroll
        for (int u = 0; u < 2; u++) {
            int rr = roff + u;
            long r = r0 + rr;
            float avR = u ? vR.y : vR.x;
            float avZ = u ? vZ.y : vZ.x;
            float avNi = u ? vNi.y : vNi.x;
            float avNh = u ? vNh.y : vNh.x;
            float hold = sxh[(DGRU+j)*XS + rr];
            float rg = sigm(avR + bR);
            float z  = sigm(avZ + bZ);
            float nn = tanhf(avNi + biN + rg*(avNh + bhN));
            float hf = (1.f - z)*nn + z*hold;   // cols 0..15: always update
            h[r*HH + j] = hf;
            part[u] += hf * fw;
        }
        if (yout) {
            #pragma unroll
            for (int k = 0; k < 3; k++) {
                int j2 = 16 + jh + k*16;
                float fw2 = fcw[j2];
                #pragma unroll
                for (int u = 0; u < 2; u++)
                    part[u] += sxh[(DGRU+j2)*XS + roff + u] * fw2;
            }
            #pragma unroll
            for (int u = 0; u < 2; u++) {
                float v = part[u];
                v += __shfl_xor_sync(0xffffffffu, v, 8);
                v += __shfl_xor_sync(0xffffffffu, v, 4);
                v += __shfl_xor_sync(0xffffffffu, v, 2);
                v += __shfl_xor_sync(0xffffffffu, v, 1);
                if (jh == 0) {
                    long r = r0 + roff + u;
                    float y = v + fcb[0];
                    ycomp[r] = y;
                    if (ynext) ynext[r*DIN] = y;
                    int b = (int)(r / nnodes), n = (int)(r % nnodes);
                    yout[((size_t)b*TP + step)*nnodes + n] = y;
                }
            }
        }
        __syncthreads();
    }
}

// ================= MEGAKERNEL =================
struct MegaP {
    const float *features, *c_features, *x_hist, *c_x_hist;
    const float *adj_sta, *adj_city, *afc;
    const float *gwi_s, *gwh_s, *gbi_s, *gbh_s;
    const float *gwi_c, *gwh_c, *gbi_c, *gbh_c;
    const float *conv_w, *conv_b, *c_conv_w, *c_conv_b;
    const float *c2s_w, *c2s_b, *s2c_w, *s2c_b;
    const float *fc_w, *fc_b, *c_fc_w, *c_fc_b;
    float *out_s, *out_c;
};

#define SCRATCH_FLOATS (56*64 + 64 + 64*64 + 56*XS + 64*XS + 64)
#define MEGA_SMEM_FLOATS (DGRU*NG + HH*NG + NG + NG + SCRATCH_FLOATS)

__global__ __launch_bounds__(NTHR, 1) void k_mega(MegaP P) {
    extern __shared__ float sm[];
    float* swi = sm;
    float* swh = swi + DGRU*NG;
    float* sbi = swh + HH*NG;
    float* sbh = sbi + NG;
    float* scratch = sbh + NG;

    int bid = blockIdx.x, tid = threadIdx.x;
    bool isC = bid >= NBLK_S;
    int t0 = isC ? (bid - NBLK_S) : bid;
    int tstep = isC ? NBLK_C : NBLK_S;

    // persistent GRU weights
    {
        const float* wi = isC ? P.gwi_c : P.gwi_s;
        const float* wh = isC ? P.gwh_c : P.gwh_s;
        const float* bi = isC ? P.gbi_c : P.gbi_s;
        const float* bh = isC ? P.gbh_c : P.gbh_s;
        for (int i = tid; i < DGRU*NG; i += NTHR) swi[i] = wi[i];
        for (int i = tid; i < HH*NG; i += NTHR) swh[i] = wh[i];
        if (tid < NG) { sbi[tid] = bi[tid]; sbh[tid] = bh[tid]; }
    }

    hist_stage_phase(P.x_hist, P.features, P.c_x_hist, P.c_features);
    buildpx_phase(P.features, P.c_features);
    counts_phase(P.adj_sta, P.afc, P.adj_city);
    gbar();
    scan_phase(scratch);
    gbar();
    fills_phase(P.adj_sta, P.afc, P.adj_city);
    gbar();
    prep2_phase(P.x_hist, P.c_x_hist);
    gbar();
    // history cheb (+z only for cities)
    if (!isC)
        chebz_phase(scratch, g_xs, g_Lxs, P.conv_w, P.conv_b, nullptr,
                    g_xgs, nullptr, t0, tstep, (THIST*RS) >> 7, 0, nullptr, 0);
    else
        chebz_phase(scratch, g_xc, g_Lxc, P.c_conv_w, P.c_conv_b, P.c2s_w,
                    g_xgc, g_zch, t0, tstep, (THIST*RC) >> 7, 0, nullptr, 1);
    gbar();
    // history GRU (7 steps, scatter fused)
    #pragma unroll 1
    for (int t = 0; t < THIST; t++) {
        int idx = 1 + t;
        bool full = ((idx & 3) == 0);
        bool odd  = ((idx & 1) != 0);
        if (!isC) {
            if (full)
                gru_phase<2,false>(swi, swh, sbi, sbh, scratch,
                      g_xs + (size_t)t*RS*DIN, g_xgs + (size_t)t*RS*GF,
                      g_zch + (size_t)t*RC*GF, P.c2s_b,
                      g_afc_rowptr, g_afc_cols, NCIT*16, 12,
                      g_hs, t0, tstep, RS >> 7, idx,
                      nullptr, nullptr, nullptr, nullptr, nullptr, NSTA, 0, nullptr);
            else if (odd)
                gruh_phase<false>(swi, swh, sbi, sbh, scratch,
                      g_xs + (size_t)t*RS*DIN, g_xgs + (size_t)t*RS*GF,
                      g_zch + (size_t)t*RC*GF, P.c2s_b,
                      g_afc_rowptr, g_afc_cols, NCIT*16, 12,
                      g_hs, t0, tstep, RS >> 7,
                      nullptr, nullptr, nullptr, nullptr, nullptr, NSTA, 0, nullptr);
            else
                gru_phase<1,false>(swi, swh, sbi, sbh, scratch,
                      g_xs + (size_t)t*RS*DIN, g_xgs + (size_t)t*RS*GF,
                      g_zch + (size_t)t*RC*GF, P.c2s_b,
                      g_afc_rowptr, g_afc_cols, NCIT*16, 12,
                      g_hs, t0, tstep, RS >> 7, idx,
                      nullptr, nullptr, nullptr, nullptr, nullptr, NSTA, 0, nullptr);
        } else {
            if (full)
                gru_phase<2,true>(swi, swh, sbi, sbh, scratch,
                      g_xc + (size_t)t*RC*DIN, g_xgc + (size_t)t*RC*GF,
                      g_xgs + (size_t)t*RS*GF, P.s2c_b,
                      g_afcT_rowptr, g_afcT_cols, NSTA*16, 8,
                      g_hc, t0, tstep, RC >> 7, idx,
                      nullptr, nullptr, nullptr, nullptr, nullptr, NCIT, 0, P.s2c_w);
            else if (odd)
                gruh_phase<true>(swi, swh, sbi, sbh, scratch,
                      g_xc + (size_t)t*RC*DIN, g_xgc + (size_t)t*RC*GF,
                      g_xgs + (size_t)t*RS*GF, P.s2c_b,
                      g_afcT_rowptr, g_afcT_cols, NSTA*16, 8,
                      g_hc, t0, tstep, RC >> 7,
                      nullptr, nullptr, nullptr, nullptr, nullptr, NCIT, 0, P.s2c_w);
            else
                gru_phase<1,true>(swi, swh, sbi, sbh, scratch,
                      g_xc + (size_t)t*RC*DIN, g_xgc + (size_t)t*RC*GF,
                      g_xgs + (size_t)t*RS*GF, P.s2c_b,
                      g_afcT_rowptr, g_afcT_cols, NSTA*16, 8,
                      g_hc, t0, tstep, RC >> 7, idx,
                      nullptr, nullptr, nullptr, nullptr, nullptr, NCIT, 0, P.s2c_w);
        }
        gbar();
    }
    // pred loop (24 steps, 2 phases each)
    #pragma unroll 1
    for (int s = 0; s < TP; s++) {
        int idx = TH + s;
        bool full = ((idx & 3) == 0);
        bool odd  = ((idx & 1) != 0);
        float* pxs_s  = g_pxs  + (size_t)s*SPS;
        float* pLxs_s = g_pLxs + (size_t)s*SPS;
        float* pxc_s  = g_pxc  + (size_t)s*SPC;
        float* pLxc_s = g_pLxc + (size_t)s*SPC;
        if (!isC)
            chebz_phase(scratch, pxs_s, pLxs_s, P.conv_w, P.conv_b, nullptr,
                        g_xgs, nullptr, t0, tstep, RS >> 7, 1, g_ys, 0);
        else
            chebz_phase(scratch, pxc_s, pLxc_s, P.c_conv_w, P.c_conv_b, P.c2s_w,
                        g_xgc, g_zch, t0, tstep, RC >> 7, 2, g_yc, 1);
        gbar();
        float* ynext_s = (s + 1 < TP) ? (g_pxs + (size_t)(s+1)*SPS) : nullptr;
        float* ynext_c = (s + 1 < TP) ? (g_pxc + (size_t)(s+1)*SPC) : nullptr;
        if (!isC) {
            if (full)
                gru_phase<2,false>(swi, swh, sbi, sbh, scratch,
                      pxs_s, g_xgs, g_zch, P.c2s_b,
                      g_afc_rowptr, g_afc_cols, NCIT*16, 12,
                      g_hs, t0, tstep, RS >> 7, idx,
                      P.fc_w, P.fc_b, g_ys, ynext_s, P.out_s, NSTA, s, nullptr);
            else if (odd)
                gruh_phase<false>(swi, swh, sbi, sbh, scratch,
                      pxs_s, g_xgs, g_zch, P.c2s_b,
                      g_afc_rowptr, g_afc_cols, NCIT*16, 12,
                      g_hs, t0, tstep, RS >> 7,
                      P.fc_w, P.fc_b, g_ys, ynext_s, P.out_s, NSTA, s, nullptr);
            else
                gru_phase<1,false>(swi, swh, sbi, sbh, scratch,
                      pxs_s, g_xgs, g_zch, P.c2s_b,
                      g_afc_rowptr, g_afc_cols, NCIT*16, 12,
                      g_hs, t0, tstep, RS >> 7, idx,
                      P.fc_w, P.fc_b, g_ys, ynext_s, P.out_s, NSTA, s, nullptr);
        } else {
            if (full)
                gru_phase<2,true>(swi, swh, sbi, sbh, scratch,
                      pxc_s, g_xgc, g_xgs, P.s2c_b,
                      g_afcT_rowptr, g_afcT_cols, NSTA*16, 8,
                      g_hc, t0, tstep, RC >> 7, idx,
                      P.c_fc_w, P.c_fc_b, g_yc, ynext_c, P.out_c, NCIT, s, P.s2c_w);
            else if (odd)
                gruh_phase<true>(swi, swh, sbi, sbh, scratch,
                      pxc_s, g_xgc, g_xgs, P.s2c_b,
                      g_afcT_rowptr, g_afcT_cols, NSTA*16, 8,
                      g_hc, t0, tstep, RC >> 7,
                      P.c_fc_w, P.c_fc_b, g_yc, ynext_c, P.out_c, NCIT, s, P.s2c_w);
            else
                gru_phase<1,true>(swi, swh, sbi, sbh, scratch,
                      pxc_s, g_xgc, g_xgs, P.s2c_b,
                      g_afcT_rowptr, g_afcT_cols, NSTA*16, 8,
                      g_hc, t0, tstep, RC >> 7, idx,
                      P.c_fc_w, P.c_fc_b, g_yc, ynext_c, P.out_c, NCIT, s, P.s2c_w);
        }
        gbar();
    }
}

// ---------------- host ----------------
extern "C" void kernel_launch(void* const* d_in, const int* in_sizes, int n_in,
                              void* d_out, int out_size) {
    MegaP P;
    P.x_hist     = (const float*)d_in[0];
    P.features   = (const float*)d_in[1];
    P.c_x_hist   = (const float*)d_in[2];
    P.c_features = (const float*)d_in[3];
    P.adj_sta    = (const float*)d_in[4];
    P.adj_city   = (const float*)d_in[5];
    P.afc        = (const float*)d_in[6];
    P.conv_w     = (const float*)d_in[7];
    P.conv_b     = (const float*)d_in[8];
    P.c_conv_w   = (const float*)d_in[9];
    P.c_conv_b   = (const float*)d_in[10];
    P.gwi_s      = (const float*)d_in[11];
    P.gwh_s      = (const float*)d_in[12];
    P.gbi_s      = (const float*)d_in[13];
    P.gbh_s      = (const float*)d_in[14];
    P.gwi_c      = (const float*)d_in[15];
    P.gwh_c      = (const float*)d_in[16];
    P.gbi_c      = (const float*)d_in[17];
    P.gbh_c      = (const float*)d_in[18];
    P.fc_w       = (const float*)d_in[19];
    P.fc_b       = (const float*)d_in[20];
    P.c_fc_w     = (const float*)d_in[21];
    P.c_fc_b     = (const float*)d_in[22];
    P.c2s_w      = (const float*)d_in[23];
    P.c2s_b      = (const float*)d_in[24];
    P.s2c_w      = (const float*)d_in[25];
    P.s2c_b      = (const float*)d_in[26];
    P.out_s = (float*)d_out;
    P.out_c = P.out_s + (size_t)NB * TP * NSTA;

    (void)in_sizes; (void)n_in; (void)out_size;

    const int mega_smem = MEGA_SMEM_FLOATS * (int)sizeof(float);
    cudaFuncSetAttribute(k_mega, cudaFuncAttributeMaxDynamicSharedMemorySize, mega_smem);
    k_mega<<<NBLK, NTHR, mega_smem>>>(P);
}